// round 9
// baseline (speedup 1.0000x reference)
#include <cuda_runtime.h>
#include <math.h>
#include <stdint.h>

// Problem constants
#define T_      80
#define BS_     8
#define DM_     768
#define H_      4
#define DH_     192
#define FF_     1024
#define L_      4
#define LATENT_ 256
#define ROWS_   (T_ * BS_)      // 640
#define NJF_    150
#define A_      6

#define EPS_ATT 1e-6f
#define EPS_LN  1e-5f

// ---------------------------------------------------------------------------
// Scratch — device globals only; selected device-side via integer codes so
// kernel_launch is pure kernel launches (graph-capture safe).
// ---------------------------------------------------------------------------
__device__ float g_h  [ROWS_ * DM_];
__device__ float g_h1 [ROWS_ * DM_];
__device__ float g_q  [ROWS_ * DM_];
__device__ float g_k  [ROWS_ * DM_];
__device__ float g_v  [ROWS_ * DM_];
__device__ float g_att[ROWS_ * DM_];
__device__ float g_ff [ROWS_ * FF_];

#define BUF_H   0
#define BUF_H1  1
#define BUF_Q   2
#define BUF_K   3
#define BUF_V   4
#define BUF_ATT 5
#define BUF_FF  6

__device__ __forceinline__ float* scratch(int code)
{
    switch (code) {
        case BUF_H:   return g_h;
        case BUF_H1:  return g_h1;
        case BUF_Q:   return g_q;
        case BUF_K:   return g_k;
        case BUF_V:   return g_v;
        case BUF_ATT: return g_att;
        default:      return g_ff;
    }
}

// ---------------------------------------------------------------------------
// h0: skeleton embedding + mu/sigma query gather + positional encoding
// ---------------------------------------------------------------------------
__global__ void build_h0_kernel(const float* __restrict__ x,        // [bs,25,6,T]
                                const int*   __restrict__ y,        // [bs,A]
                                const int*   __restrict__ ind_map,  // [T,bs]
                                const float* __restrict__ skW,      // [150,256]
                                const float* __restrict__ skb,      // [256]
                                const float* __restrict__ muQ,      // [C,256]
                                const float* __restrict__ sgQ)      // [C,256]
{
    const int r = blockIdx.x;
    const int t = r / BS_;
    const int b = r - t * BS_;
    const int tid = threadIdx.x;          // 0..255

    __shared__ float xrow[NJF_];
    if (tid < NJF_) xrow[tid] = x[(size_t)b * NJF_ * T_ + tid * T_ + t];
    __syncthreads();

    const int a   = ind_map[t * BS_ + b];
    const int cls = y[b * A_ + a];
    const int start = (t == 0) ? 0 : (t + 2);

    const float div = expf(-(logf(10000.0f) / (float)LATENT_) * (float)(tid & ~1));
    const bool  odd = (tid & 1);

    float base0 = muQ[cls * LATENT_ + tid];
    float base1 = sgQ[cls * LATENT_ + tid];
    float acc = skb[tid];
    #pragma unroll 5
    for (int jf = 0; jf < NJF_; jf++) acc += xrow[jf] * skW[jf * LATENT_ + tid];

    float* dst = g_h + (size_t)r * DM_;
    {
        float ang = (float)(start + 0) * div;
        dst[tid]             = base0 + (odd ? cosf(ang) : sinf(ang));
    }
    {
        float ang = (float)(start + 1) * div;
        dst[tid + LATENT_]   = base1 + (odd ? cosf(ang) : sinf(ang));
    }
    {
        float ang = (float)(start + 2) * div;
        dst[tid + 2*LATENT_] = acc   + (odd ? cosf(ang) : sinf(ang));
    }
}

// ---------------------------------------------------------------------------
// TF32 3x-split tensor-core GEMM.
// CTA tile 64x64, BK=16, 256 threads = 8 warps: 2(m) x 2(n) x 2(k-split).
// Warp tile 32x32 (2 m16-tiles x 4 n8-tiles), k-split over the two k8 steps.
// Operands staged in smem in FRAGMENT ORDER: A-frag = one LDS.128/tile,
// B-frag = one LDS.64/tile, all conflict-free.
// act: 0 = none, 1 = elu(x)+1, 2 = relu
// ---------------------------------------------------------------------------
#define BK 16

__device__ __forceinline__ float f2tf32(float x)
{
    unsigned u;
    asm("cvt.rna.tf32.f32 %0, %1;" : "=r"(u) : "f"(x));
    return __uint_as_float(u);
}

__device__ __forceinline__ void mma_tf32(float4& c, const float4& a, const float2& b)
{
    const uint32_t* A = reinterpret_cast<const uint32_t*>(&a);
    const uint32_t* B = reinterpret_cast<const uint32_t*>(&b);
    float* C = reinterpret_cast<float*>(&c);
    asm volatile(
        "mma.sync.aligned.m16n8k8.row.col.f32.tf32.tf32.f32 "
        "{%0,%1,%2,%3}, {%4,%5,%6,%7}, {%8,%9}, {%0,%1,%2,%3};"
        : "+f"(C[0]), "+f"(C[1]), "+f"(C[2]), "+f"(C[3])
        : "r"(A[0]), "r"(A[1]), "r"(A[2]), "r"(A[3]), "r"(B[0]), "r"(B[1]));
}

__device__ __forceinline__ void gemm_core(const float* __restrict__ A,
                                          const float* __restrict__ B,
                                          const float* __restrict__ bias,
                                          float* __restrict__ C,
                                          int N, int K,
                                          int rowBase, int colBase, int act)
{
    // smem pool: sAh[1024] sAl[1024] sBh[1024] sBl[1024]  (16 KB)
    __shared__ __align__(16) float spool[4096];
    float* sAh = spool;
    float* sAl = spool + 1024;
    float* sBh = spool + 2048;
    float* sBl = spool + 3072;

    const int tid   = threadIdx.x;
    const int lane  = tid & 31;
    const int wid   = tid >> 5;
    const int warp_m = wid & 1;
    const int warp_n = (wid >> 1) & 1;
    const int warp_k = wid >> 2;
    const int g = lane >> 2;
    const int t = lane & 3;

    // gmem tile writer coords
    const int ar  = tid >> 2;            // 0..63   (A row in tile)
    const int ac4 = (tid & 3) << 2;      // 0,4,8,12
    const int br  = tid >> 4;            // 0..15   (B row (k) in tile)
    const int bc4 = (tid & 15) << 2;     // 0..60

    // fragment-order scatter destinations for this thread's 4 A / 4 B elems
    int adst[4], bdst[4];
    #pragma unroll
    for (int j = 0; j < 4; j++) {
        // A element (row=ar, col=ac4+j) within the 64x16 tile
        int c  = ac4 + j;
        int s_ = c >> 3, cc = c & 7, t_ = cc & 3, jh = cc >> 2;
        int mi = ar >> 4, r8 = (ar >> 3) & 1, g_ = ar & 7;
        adst[j] = (((s_ * 4 + mi) * 32) + (g_ * 4 + t_)) * 4 + (r8 + jh * 2);
        // B element (k=br, col=bc4+j) within the 16x64 tile
        int cB = bc4 + j;
        int sB = br >> 3, kk = br & 7, tB = kk & 3, tb = kk >> 2;
        int ni = cB >> 3, gB = cB & 7;
        bdst[j] = (((sB * 8 + ni) * 32) + (gB * 4 + tB)) * 2 + tb;
    }

    const float* Aptr = A + (size_t)(rowBase + ar) * K + ac4;
    const float* Bptr = B + (size_t)br * N + colBase + bc4;

    float4 acc[2][4];
    #pragma unroll
    for (int mt = 0; mt < 2; mt++)
        #pragma unroll
        for (int nt = 0; nt < 4; nt++)
            acc[mt][nt] = make_float4(0.f, 0.f, 0.f, 0.f);

    const int KT = K / BK;
    float4 av = *(const float4*)Aptr;
    float4 bv = *(const float4*)Bptr;

    for (int kt = 0; kt < KT; kt++) {
        __syncthreads();   // previous iter's frag reads complete
        {
            const float va[4] = {av.x, av.y, av.z, av.w};
            const float vb[4] = {bv.x, bv.y, bv.z, bv.w};
            #pragma unroll
            for (int j = 0; j < 4; j++) {
                float hiA = f2tf32(va[j]);
                sAh[adst[j]] = hiA;
                sAl[adst[j]] = f2tf32(va[j] - hiA);
                float hiB = f2tf32(vb[j]);
                sBh[bdst[j]] = hiB;
                sBl[bdst[j]] = f2tf32(vb[j] - hiB);
            }
        }
        __syncthreads();

        if (kt + 1 < KT) {   // prefetch next tile early — hide gmem latency
            av = *(const float4*)(Aptr + (kt + 1) * BK);
            bv = *(const float4*)(Bptr + (size_t)(kt + 1) * BK * N);
        }

        // fragment loads (conflict-free vector LDS)
        float4 ah[2], al[2];
        float2 bh[4], bl[4];
        #pragma unroll
        for (int mt = 0; mt < 2; mt++) {
            int idx = (warp_k * 4 + warp_m * 2 + mt) * 32 + lane;
            ah[mt] = *(const float4*)(sAh + idx * 4);
            al[mt] = *(const float4*)(sAl + idx * 4);
        }
        #pragma unroll
        for (int nt = 0; nt < 4; nt++) {
            int idx = (warp_k * 8 + warp_n * 4 + nt) * 32 + lane;
            bh[nt] = *(const float2*)(sBh + idx * 2);
            bl[nt] = *(const float2*)(sBl + idx * 2);
        }

        #pragma unroll
        for (int mt = 0; mt < 2; mt++)
            #pragma unroll
            for (int nt = 0; nt < 4; nt++) {
                mma_tf32(acc[mt][nt], ah[mt], bh[nt]);   // hi*hi
                mma_tf32(acc[mt][nt], ah[mt], bl[nt]);   // hi*lo
                mma_tf32(acc[mt][nt], al[mt], bh[nt]);   // lo*hi
            }
    }

    // k-split reduction: warps 4-7 dump accs, warps 0-3 add.
    __syncthreads();
    if (warp_k == 1) {
        const float* accF = reinterpret_cast<const float*>(acc);
        int base = (wid - 4) * 32 + lane;
        #pragma unroll
        for (int j = 0; j < 32; j++) spool[j * 128 + base] = accF[j];
    }
    __syncthreads();
    if (warp_k == 0) {
        float* accF = reinterpret_cast<float*>(acc);
        int base = wid * 32 + lane;
        #pragma unroll
        for (int j = 0; j < 32; j++) accF[j] += spool[j * 128 + base];

        #pragma unroll
        for (int mt = 0; mt < 2; mt++) {
            int row0 = rowBase + warp_m * 32 + mt * 16 + g;
            #pragma unroll
            for (int nt = 0; nt < 4; nt++) {
                int col = colBase + warp_n * 32 + nt * 8 + 2 * t;
                float2 bsv = *(const float2*)(bias + col);
                float4 cv = acc[mt][nt];
                float o0 = cv.x + bsv.x, o1 = cv.y + bsv.y;
                float o2 = cv.z + bsv.x, o3 = cv.w + bsv.y;
                if (act == 1) {
                    o0 = (o0 > 0.f) ? (o0 + 1.f) : expf(o0);
                    o1 = (o1 > 0.f) ? (o1 + 1.f) : expf(o1);
                    o2 = (o2 > 0.f) ? (o2 + 1.f) : expf(o2);
                    o3 = (o3 > 0.f) ? (o3 + 1.f) : expf(o3);
                } else if (act == 2) {
                    o0 = fmaxf(o0, 0.f); o1 = fmaxf(o1, 0.f);
                    o2 = fmaxf(o2, 0.f); o3 = fmaxf(o3, 0.f);
                }
                *(float2*)(C + (size_t)row0 * N + col)       = make_float2(o0, o1);
                *(float2*)(C + (size_t)(row0 + 8) * N + col) = make_float2(o2, o3);
            }
        }
    }
}

__global__ void gemm_kernel(int a_code, const float* __restrict__ B,
                            const float* __restrict__ bias, int c_code,
                            int N, int K, int act)
{
    gemm_core(scratch(a_code), B, bias, scratch(c_code),
              N, K, blockIdx.y * 64, blockIdx.x * 64, act);
}

// Fused QKV: virtual N = 3*768; each 64-col block belongs to one matrix
__global__ void gemm_qkv_kernel(const float* __restrict__ Wq, const float* __restrict__ Wk,
                                const float* __restrict__ Wv,
                                const float* __restrict__ bq, const float* __restrict__ bk,
                                const float* __restrict__ bv)
{
    const int gcol = blockIdx.x * 64;
    const int mat  = gcol / DM_;
    const int colBase = gcol - mat * DM_;
    const float* B    = (mat == 0) ? Wq  : (mat == 1) ? Wk  : Wv;
    const float* bias = (mat == 0) ? bq  : (mat == 1) ? bk  : bv;
    float*       C    = (mat == 0) ? g_q : (mat == 1) ? g_k : g_v;
    const int act     = (mat < 2) ? 1 : 0;   // elu+1 on Q,K; none on V
    gemm_core(g_h, B, bias, C, DM_, DM_, blockIdx.y * 64, colBase, act);
}

// ---------------------------------------------------------------------------
// Causal linear attention, tiled. Grid (chunk=4, bh=32); 256 threads.
// ---------------------------------------------------------------------------
#define CHUNK 20
#define ALD   193

__global__ void attn_kernel()
{
    __shared__ float Qs [CHUNK][ALD];
    __shared__ float KVs[CHUNK][ALD];
    __shared__ float Asc[CHUNK][T_];
    __shared__ float inv[CHUNK];

    const int chunk = blockIdx.x;      // 0..3
    const int bh    = blockIdx.y;      // 0..31
    const int b  = bh >> 2;
    const int h  = bh & 3;
    const int t0 = chunk * CHUNK;
    const int tid = threadIdx.x;

    for (int i = tid; i < CHUNK * DH_; i += 256) {
        int tl = i / DH_, d = i - tl * DH_;
        Qs[tl][d] = g_q[(size_t)((t0 + tl) * BS_ + b) * DM_ + h * DH_ + d];
    }
    __syncthreads();

    for (int tt = 0; tt <= chunk; tt++) {
        const int tauBase = tt * CHUNK;
        for (int i = tid; i < CHUNK * DH_; i += 256) {
            int j = i / DH_, d = i - j * DH_;
            KVs[j][d] = g_k[(size_t)((tauBase + j) * BS_ + b) * DM_ + h * DH_ + d];
        }
        __syncthreads();

        for (int p = tid; p < CHUNK * CHUNK; p += 256) {
            int tl = p / CHUNK, tj = p - tl * CHUNK;
            float s = 0.0f;
            if (tauBase + tj <= t0 + tl) {
                #pragma unroll 8
                for (int d = 0; d < DH_; d++) s += Qs[tl][d] * KVs[tj][d];
            }
            Asc[tl][tauBase + tj] = s;
        }
        __syncthreads();
    }

    const int width = (chunk + 1) * CHUNK;
    if (tid < CHUNK) {
        float s = 0.0f;
        for (int tau = 0; tau < width; tau++) s += Asc[tid][tau];
        inv[tid] = 1.0f / (s + EPS_ATT);
    }
    __syncthreads();

    float acc[(CHUNK * DH_ + 255) / 256] = {};
    for (int tt = 0; tt <= chunk; tt++) {
        const int tauBase = tt * CHUNK;
        for (int i = tid; i < CHUNK * DH_; i += 256) {
            int j = i / DH_, d = i - j * DH_;
            KVs[j][d] = g_v[(size_t)((tauBase + j) * BS_ + b) * DM_ + h * DH_ + d];
        }
        __syncthreads();

        #pragma unroll
        for (int it = 0; it < (CHUNK * DH_ + 255) / 256; it++) {
            int idx = tid + it * 256;
            int tl = idx / DH_, d = idx - tl * DH_;
            float a = 0.0f;
            #pragma unroll
            for (int j = 0; j < CHUNK; j++) a += Asc[tl][tauBase + j] * KVs[j][d];
            acc[it] += a;
        }
        __syncthreads();
    }

    #pragma unroll
    for (int it = 0; it < (CHUNK * DH_ + 255) / 256; it++) {
        int idx = tid + it * 256;
        int tl = idx / DH_, d = idx - tl * DH_;
        g_att[(size_t)((t0 + tl) * BS_ + b) * DM_ + h * DH_ + d] = acc[it] * inv[tl];
    }
}

// ---------------------------------------------------------------------------
// LayerNorm helpers
// ---------------------------------------------------------------------------
__device__ __forceinline__ float block_sum_256(float val)
{
    __shared__ float sh[8];
    const int lane = threadIdx.x & 31;
    const int w    = threadIdx.x >> 5;
    #pragma unroll
    for (int o = 16; o > 0; o >>= 1) val += __shfl_down_sync(0xffffffffu, val, o);
    if (lane == 0) sh[w] = val;
    __syncthreads();
    if (w == 0) {
        float r = (lane < 8) ? sh[lane] : 0.0f;
        #pragma unroll
        for (int o = 4; o > 0; o >>= 1) r += __shfl_down_sync(0xffffffffu, r, o);
        if (lane == 0) sh[0] = r;
    }
    __syncthreads();
    float res = sh[0];
    __syncthreads();
    return res;
}

__global__ void ln_residual_kernel(int x_code, int y_code,
                                   const float* __restrict__ g, const float* __restrict__ bt,
                                   int out_code)
{
    const float* x  = scratch(x_code);
    const float* yv = scratch(y_code);
    float* out      = scratch(out_code);

    const int row = blockIdx.x;
    const int tid = threadIdx.x;
    const size_t base = (size_t)row * DM_;

    float v0 = x[base + tid]       + yv[base + tid];
    float v1 = x[base + tid + 256] + yv[base + tid + 256];
    float v2 = x[base + tid + 512] + yv[base + tid + 512];

    float mean = block_sum_256(v0 + v1 + v2) * (1.0f / (float)DM_);
    float d0 = v0 - mean, d1 = v1 - mean, d2 = v2 - mean;
    float var = block_sum_256(d0*d0 + d1*d1 + d2*d2) * (1.0f / (float)DM_);
    float rstd = rsqrtf(var + EPS_LN);

    out[base + tid]       = d0 * rstd * g[tid]       + bt[tid];
    out[base + tid + 256] = d1 * rstd * g[tid + 256] + bt[tid + 256];
    out[base + tid + 512] = d2 * rstd * g[tid + 512] + bt[tid + 512];
}

// ---------------------------------------------------------------------------
// Final: gather selected rows, final LN, emit mu || logvar
// ---------------------------------------------------------------------------
__global__ void gather_kernel(const int* __restrict__ act_ts,
                              const float* __restrict__ g, const float* __restrict__ bt,
                              float* __restrict__ out)
{
    const int ba = blockIdx.x;            // b*A + a
    const int b  = ba / A_;
    int t = act_ts[ba] - 1;
    if (t < 0) t = 0;
    const int row = t * BS_ + b;
    const int tid = threadIdx.x;
    const size_t base = (size_t)row * DM_;

    float v0 = g_h[base + tid];
    float v1 = g_h[base + tid + 256];
    float v2 = g_h[base + tid + 512];

    float mean = block_sum_256(v0 + v1 + v2) * (1.0f / (float)DM_);
    float d0 = v0 - mean, d1 = v1 - mean, d2 = v2 - mean;
    float var = block_sum_256(d0*d0 + d1*d1 + d2*d2) * (1.0f / (float)DM_);
    float rstd = rsqrtf(var + EPS_LN);

    out[(size_t)ba * LATENT_ + tid]                      = d0 * rstd * g[tid]       + bt[tid];
    out[(size_t)BS_ * A_ * LATENT_ + ba * LATENT_ + tid] = d1 * rstd * g[tid + 256] + bt[tid + 256];
}

// ---------------------------------------------------------------------------
// Host orchestration: kernel launches ONLY (graph-capture safe)
// ---------------------------------------------------------------------------
extern "C" void kernel_launch(void* const* d_in, const int* in_sizes, int n_in,
                              void* d_out, int out_size)
{
    const float* x    = (const float*)d_in[0];
    const int*   y    = (const int*)  d_in[1];
    const int*   ind  = (const int*)  d_in[2];
    const int*   ats  = (const int*)  d_in[3];
    const float* skW  = (const float*)d_in[4];
    const float* skb  = (const float*)d_in[5];
    const float* muQ  = (const float*)d_in[6];
    const float* sgQ  = (const float*)d_in[7];
    const float* Wq   = (const float*)d_in[8];
    const float* bq   = (const float*)d_in[9];
    const float* Wk   = (const float*)d_in[10];
    const float* bk   = (const float*)d_in[11];
    const float* Wv   = (const float*)d_in[12];
    const float* bv   = (const float*)d_in[13];
    const float* Wo   = (const float*)d_in[14];
    const float* bo   = (const float*)d_in[15];
    const float* W1   = (const float*)d_in[16];
    const float* b1   = (const float*)d_in[17];
    const float* W2   = (const float*)d_in[18];
    const float* b2   = (const float*)d_in[19];
    const float* l1g  = (const float*)d_in[20];
    const float* l1b  = (const float*)d_in[21];
    const float* l2g  = (const float*)d_in[22];
    const float* l2b  = (const float*)d_in[23];
    const float* lfg  = (const float*)d_in[24];
    const float* lfb  = (const float*)d_in[25];
    float* out = (float*)d_out;

    build_h0_kernel<<<ROWS_, 256>>>(x, y, ind, skW, skb, muQ, sgQ);

    const dim3 gQKV(3 * DM_ / 64, ROWS_ / 64);   // 36 x 10
    const dim3 g768(DM_ / 64, ROWS_ / 64);       // 12 x 10
    const dim3 g1024(FF_ / 64, ROWS_ / 64);      // 16 x 10
    const dim3 gAttn(4, BS_ * H_);               // 4 chunks x 32 (b,h)

    for (int l = 0; l < L_; l++) {
        gemm_qkv_kernel<<<gQKV, 256>>>(Wq + (size_t)l * DM_ * DM_,
                                       Wk + (size_t)l * DM_ * DM_,
                                       Wv + (size_t)l * DM_ * DM_,
                                       bq + l * DM_, bk + l * DM_, bv + l * DM_);
        attn_kernel<<<gAttn, 256>>>();
        gemm_kernel<<<g768, 256>>>(BUF_ATT, Wo + (size_t)l * DM_ * DM_, bo + l * DM_,
                                   BUF_Q, DM_, DM_, 0);
        ln_residual_kernel<<<ROWS_, 256>>>(BUF_H, BUF_Q, l1g + l * DM_, l1b + l * DM_, BUF_H1);
        gemm_kernel<<<g1024, 256>>>(BUF_H1, W1 + (size_t)l * DM_ * FF_, b1 + l * FF_,
                                    BUF_FF, FF_, DM_, 2);
        gemm_kernel<<<g768, 256>>>(BUF_FF, W2 + (size_t)l * FF_ * DM_, b2 + l * DM_,
                                   BUF_Q, DM_, FF_, 0);
        ln_residual_kernel<<<ROWS_, 256>>>(BUF_H1, BUF_Q, l2g + l * DM_, l2b + l * DM_, BUF_H);
    }

    gather_kernel<<<BS_ * A_, 256>>>(ats, lfg, lfb, out);
}

// round 10
// speedup vs baseline: 2.7725x; 2.7725x over previous
#include <cuda_runtime.h>
#include <cuda_bf16.h>
#include <math.h>
#include <stdint.h>

// Problem constants
#define T_      80
#define BS_     8
#define DM_     768
#define H_      4
#define DH_     192
#define FF_     1024
#define L_      4
#define LATENT_ 256
#define ROWS_   (T_ * BS_)      // 640
#define NJF_    150
#define A_      6

#define EPS_ATT 1e-6f
#define EPS_LN  1e-5f

typedef __nv_bfloat16 bf16;

// ---------------------------------------------------------------------------
// Scratch (device globals only; no cudaMalloc anywhere)
// ---------------------------------------------------------------------------
__device__ __align__(16) float g_h [ROWS_ * DM_];
__device__ __align__(16) float g_h1[ROWS_ * DM_];
__device__ __align__(16) float g_q [ROWS_ * DM_];
__device__ __align__(16) float g_k [ROWS_ * DM_];
__device__ __align__(16) float g_v [ROWS_ * DM_];

#define BUF_H   0
#define BUF_H1  1
#define BUF_Q   2

__device__ __forceinline__ float* scratch(int code)
{
    switch (code) {
        case BUF_H:  return g_h;
        case BUF_H1: return g_h1;
        default:     return g_q;
    }
}

// bf16 hi/lo split activations (GEMM A-operands)
__device__ __align__(16) bf16 s_h_hi  [ROWS_ * DM_];
__device__ __align__(16) bf16 s_h_lo  [ROWS_ * DM_];
__device__ __align__(16) bf16 s_att_hi[ROWS_ * DM_];
__device__ __align__(16) bf16 s_att_lo[ROWS_ * DM_];
__device__ __align__(16) bf16 s_h1_hi [ROWS_ * DM_];
__device__ __align__(16) bf16 s_h1_lo [ROWS_ * DM_];
__device__ __align__(16) bf16 s_ff_hi [ROWS_ * FF_];
__device__ __align__(16) bf16 s_ff_lo [ROWS_ * FF_];

#define SPL_H   0
#define SPL_ATT 1
#define SPL_H1  2
#define SPL_FF  3

__device__ __forceinline__ const bf16* split_hi(int c)
{
    switch (c) { case SPL_H: return s_h_hi; case SPL_ATT: return s_att_hi;
                 case SPL_H1: return s_h1_hi; default: return s_ff_hi; }
}
__device__ __forceinline__ const bf16* split_lo(int c)
{
    switch (c) { case SPL_H: return s_h_lo; case SPL_ATT: return s_att_lo;
                 case SPL_H1: return s_h1_lo; default: return s_ff_lo; }
}
__device__ __forceinline__ bf16* split_hi_w(int c)
{
    switch (c) { case SPL_H: return s_h_hi; case SPL_ATT: return s_att_hi;
                 case SPL_H1: return s_h1_hi; default: return s_ff_hi; }
}
__device__ __forceinline__ bf16* split_lo_w(int c)
{
    switch (c) { case SPL_H: return s_h_lo; case SPL_ATT: return s_att_lo;
                 case SPL_H1: return s_h1_lo; default: return s_ff_lo; }
}

__device__ __forceinline__ void split_store(float v, bf16* hi, bf16* lo, size_t idx)
{
    bf16 h = __float2bfloat16_rn(v);
    hi[idx] = h;
    lo[idx] = __float2bfloat16_rn(v - __bfloat162float(h));
}

// bf16 hi/lo split weights (GEMM B-operands), one big pool each
#define SZW_ATT (L_ * DM_ * DM_)                 // 2359296 per matrix
#define SZW_FF  (L_ * DM_ * FF_)                 // 3145728 per matrix
#define OFF_WQ  ((size_t)0)
#define OFF_WK  ((size_t)SZW_ATT)
#define OFF_WV  ((size_t)(2 * SZW_ATT))
#define OFF_WO  ((size_t)(3 * SZW_ATT))
#define OFF_W1  ((size_t)(4 * SZW_ATT))
#define OFF_W2  ((size_t)(4 * SZW_ATT) + SZW_FF)
#define TOTALW  ((size_t)(4 * SZW_ATT) + 2 * (size_t)SZW_FF)   // 15728640

__device__ __align__(16) bf16 s_W_hi[TOTALW];
__device__ __align__(16) bf16 s_W_lo[TOTALW];

// ---------------------------------------------------------------------------
// Weight splitter: run once per launch. float4-vectorized.
// ---------------------------------------------------------------------------
__global__ void split_weights_kernel(const float* __restrict__ Wq, const float* __restrict__ Wk,
                                     const float* __restrict__ Wv, const float* __restrict__ Wo,
                                     const float* __restrict__ W1, const float* __restrict__ W2)
{
    size_t i4 = ((size_t)blockIdx.x * blockDim.x + threadIdx.x) * 4;
    if (i4 >= TOTALW) return;

    const float* src;
    size_t rel;
    if (i4 < OFF_W1) {
        size_t seg = i4 / (size_t)SZW_ATT;
        rel = i4 - seg * (size_t)SZW_ATT;
        src = (seg == 0) ? Wq : (seg == 1) ? Wk : (seg == 2) ? Wv : Wo;
    } else if (i4 < OFF_W2) {
        src = W1; rel = i4 - OFF_W1;
    } else {
        src = W2; rel = i4 - OFF_W2;
    }

    float4 x = *(const float4*)(src + rel);
    const float xs[4] = {x.x, x.y, x.z, x.w};
    #pragma unroll
    for (int j = 0; j < 4; j++)
        split_store(xs[j], s_W_hi, s_W_lo, i4 + j);
}

// ---------------------------------------------------------------------------
// h0: skeleton embedding + query gathers + PE; writes fp32 + bf16 split
// ---------------------------------------------------------------------------
__global__ void build_h0_kernel(const float* __restrict__ x,
                                const int*   __restrict__ y,
                                const int*   __restrict__ ind_map,
                                const float* __restrict__ skW,
                                const float* __restrict__ skb,
                                const float* __restrict__ muQ,
                                const float* __restrict__ sgQ)
{
    const int r = blockIdx.x;
    const int t = r / BS_;
    const int b = r - t * BS_;
    const int tid = threadIdx.x;          // 0..255

    __shared__ float xrow[NJF_];
    if (tid < NJF_) xrow[tid] = x[(size_t)b * NJF_ * T_ + tid * T_ + t];
    __syncthreads();

    const int a   = ind_map[t * BS_ + b];
    const int cls = y[b * A_ + a];
    const int start = (t == 0) ? 0 : (t + 2);

    const float div = expf(-(logf(10000.0f) / (float)LATENT_) * (float)(tid & ~1));
    const bool  odd = (tid & 1);

    float base0 = muQ[cls * LATENT_ + tid];
    float base1 = sgQ[cls * LATENT_ + tid];
    float acc = skb[tid];
    #pragma unroll 5
    for (int jf = 0; jf < NJF_; jf++) acc += xrow[jf] * skW[jf * LATENT_ + tid];

    const size_t base = (size_t)r * DM_;
    float v0, v1, v2;
    { float ang = (float)(start + 0) * div; v0 = base0 + (odd ? cosf(ang) : sinf(ang)); }
    { float ang = (float)(start + 1) * div; v1 = base1 + (odd ? cosf(ang) : sinf(ang)); }
    { float ang = (float)(start + 2) * div; v2 = acc   + (odd ? cosf(ang) : sinf(ang)); }

    g_h[base + tid]             = v0;
    g_h[base + tid + LATENT_]   = v1;
    g_h[base + tid + 2*LATENT_] = v2;
    split_store(v0, s_h_hi, s_h_lo, base + tid);
    split_store(v1, s_h_hi, s_h_lo, base + tid + LATENT_);
    split_store(v2, s_h_hi, s_h_lo, base + tid + 2*LATENT_);
}

// ---------------------------------------------------------------------------
// bf16 2-term split tensor-core GEMM (m16n8k16 + ldmatrix).
// CTA tile 32x64, BK=32, 8 warps: warp_m(2) x warp_n(2) x warp_k(2).
// Warp tile m16 x n32; k-split halves reduced through smem at the end.
// ---------------------------------------------------------------------------
#define CTM 32
#define CTN 64
#define CTK 32
#define LDA_ 40     // bf16 per A smem row (32 + 8 pad)
#define LDB_ 72     // bf16 per B smem row (64 + 8 pad)

__device__ __forceinline__ uint32_t smem_u32(const void* p)
{
    return (uint32_t)__cvta_generic_to_shared(p);
}

__device__ __forceinline__ void ldm_x4(uint32_t* r, uint32_t addr)
{
    asm volatile("ldmatrix.sync.aligned.m8n8.x4.shared.b16 {%0,%1,%2,%3}, [%4];"
                 : "=r"(r[0]), "=r"(r[1]), "=r"(r[2]), "=r"(r[3]) : "r"(addr));
}
__device__ __forceinline__ void ldm_x4_t(uint32_t* r, uint32_t addr)
{
    asm volatile("ldmatrix.sync.aligned.m8n8.x4.trans.shared.b16 {%0,%1,%2,%3}, [%4];"
                 : "=r"(r[0]), "=r"(r[1]), "=r"(r[2]), "=r"(r[3]) : "r"(addr));
}
__device__ __forceinline__ void mma_bf16(float4& c, const uint32_t* a, uint32_t b0, uint32_t b1)
{
    asm volatile(
        "mma.sync.aligned.m16n8k16.row.col.f32.bf16.bf16.f32 "
        "{%0,%1,%2,%3},{%4,%5,%6,%7},{%8,%9},{%0,%1,%2,%3};"
        : "+f"(c.x), "+f"(c.y), "+f"(c.z), "+f"(c.w)
        : "r"(a[0]), "r"(a[1]), "r"(a[2]), "r"(a[3]), "r"(b0), "r"(b1));
}

__device__ __forceinline__ void gemm_bf16_core(
    const bf16* __restrict__ Ahi, const bf16* __restrict__ Alo,
    const bf16* __restrict__ Bhi, const bf16* __restrict__ Blo,
    const float* __restrict__ bias,
    float* Cf32, bf16* Shi, bf16* Slo,
    int N, int K, int rowBase, int colBase, int act, int outmode)
{
    __shared__ __align__(16) bf16 sA[2][2][CTM * LDA_];   // [buf][hi/lo]
    __shared__ __align__(16) bf16 sB[2][2][CTK * LDB_];
    __shared__ float red[2048];

    const int tid  = threadIdx.x;
    const int lane = tid & 31;
    const int wid  = tid >> 5;
    const int warp_m = wid & 1;
    const int warp_n = (wid >> 1) & 1;
    const int warp_k = wid >> 2;

    // gmem->smem writer coords
    const int matA = tid >> 7;            // 0=hi 1=lo
    const int arem = tid & 127;
    const int ar = arem >> 2, ac = arem & 3;         // A: 32 rows x 4 chunks
    const int br = tid >> 3,  bc = tid & 7;          // B: 32 rows x 8 chunks (x2 mats)

    const bf16* Asel = matA ? Alo : Ahi;
    const bf16* Agm  = Asel + (size_t)(rowBase + ar) * K + ac * 8;
    const bf16* Bgm_hi = Bhi + (size_t)br * N + colBase + bc * 8;
    const bf16* Bgm_lo = Blo + (size_t)br * N + colBase + bc * 8;

    bf16* AsmDst0 = &sA[0][matA][ar * LDA_ + ac * 8];
    bf16* AsmDst1 = &sA[1][matA][ar * LDA_ + ac * 8];
    bf16* BsmH0 = &sB[0][0][br * LDB_ + bc * 8];
    bf16* BsmH1 = &sB[1][0][br * LDB_ + bc * 8];
    bf16* BsmL0 = &sB[0][1][br * LDB_ + bc * 8];
    bf16* BsmL1 = &sB[1][1][br * LDB_ + bc * 8];

    // ldmatrix element offsets
    const int aoff  = (warp_m * 16 + (lane & 15)) * LDA_ + warp_k * 16 + (lane >> 4) * 8;
    const int boff0 = (warp_k * 16 + (lane & 15)) * LDB_ + warp_n * 32 + (lane >> 4) * 8;
    const int boff1 = boff0 + 16;

    float4 acc[4] = {{0,0,0,0},{0,0,0,0},{0,0,0,0},{0,0,0,0}};

    const int KT = K / CTK;

    // preload tile 0
    {
        uint4 pa = *(const uint4*)Agm;
        uint4 pb0 = *(const uint4*)Bgm_hi;
        uint4 pb1 = *(const uint4*)Bgm_lo;
        *(uint4*)AsmDst0 = pa;
        *(uint4*)BsmH0 = pb0;
        *(uint4*)BsmL0 = pb1;
    }
    __syncthreads();

    int buf = 0;
    for (int kt = 0; kt < KT; kt++) {
        uint4 pa, pb0, pb1;
        const bool more = (kt + 1 < KT);
        if (more) {
            pa  = *(const uint4*)(Agm + (kt + 1) * CTK);
            pb0 = *(const uint4*)(Bgm_hi + (size_t)(kt + 1) * CTK * N);
            pb1 = *(const uint4*)(Bgm_lo + (size_t)(kt + 1) * CTK * N);
        }

        uint32_t ah[4], al[4], bh0[4], bh1[4], bl0[4], bl1[4];
        ldm_x4  (ah,  smem_u32(&sA[buf][0][aoff]));
        ldm_x4  (al,  smem_u32(&sA[buf][1][aoff]));
        ldm_x4_t(bh0, smem_u32(&sB[buf][0][boff0]));
        ldm_x4_t(bh1, smem_u32(&sB[buf][0][boff1]));
        ldm_x4_t(bl0, smem_u32(&sB[buf][1][boff0]));
        ldm_x4_t(bl1, smem_u32(&sB[buf][1][boff1]));

        // nt0,nt1 from (bh0/bl0), nt2,nt3 from (bh1/bl1)
        mma_bf16(acc[0], ah, bh0[0], bh0[1]);
        mma_bf16(acc[0], ah, bl0[0], bl0[1]);
        mma_bf16(acc[0], al, bh0[0], bh0[1]);

        mma_bf16(acc[1], ah, bh0[2], bh0[3]);
        mma_bf16(acc[1], ah, bl0[2], bl0[3]);
        mma_bf16(acc[1], al, bh0[2], bh0[3]);

        mma_bf16(acc[2], ah, bh1[0], bh1[1]);
        mma_bf16(acc[2], ah, bl1[0], bl1[1]);
        mma_bf16(acc[2], al, bh1[0], bh1[1]);

        mma_bf16(acc[3], ah, bh1[2], bh1[3]);
        mma_bf16(acc[3], ah, bl1[2], bl1[3]);
        mma_bf16(acc[3], al, bh1[2], bh1[3]);

        if (more) {
            if (buf == 0) { *(uint4*)AsmDst1 = pa; *(uint4*)BsmH1 = pb0; *(uint4*)BsmL1 = pb1; }
            else          { *(uint4*)AsmDst0 = pa; *(uint4*)BsmH0 = pb0; *(uint4*)BsmL0 = pb1; }
        }
        __syncthreads();
        buf ^= 1;
    }

    // k-split reduction
    float* af = reinterpret_cast<float*>(acc);
    if (warp_k == 1) {
        int base = (wid - 4) * 32 + lane;
        #pragma unroll
        for (int j = 0; j < 16; j++) red[j * 128 + base] = af[j];
    }
    __syncthreads();
    if (warp_k == 0) {
        int base = wid * 32 + lane;
        #pragma unroll
        for (int j = 0; j < 16; j++) af[j] += red[j * 128 + base];

        const int row0 = rowBase + warp_m * 16 + (lane >> 2);
        #pragma unroll
        for (int nt = 0; nt < 4; nt++) {
            const int col = colBase + warp_n * 32 + nt * 8 + 2 * (lane & 3);
            float2 bb = *(const float2*)(bias + col);
            float v00 = acc[nt].x + bb.x, v01 = acc[nt].y + bb.y;
            float v10 = acc[nt].z + bb.x, v11 = acc[nt].w + bb.y;
            if (act == 1) {
                v00 = (v00 > 0.f) ? (v00 + 1.f) : expf(v00);
                v01 = (v01 > 0.f) ? (v01 + 1.f) : expf(v01);
                v10 = (v10 > 0.f) ? (v10 + 1.f) : expf(v10);
                v11 = (v11 > 0.f) ? (v11 + 1.f) : expf(v11);
            } else if (act == 2) {
                v00 = fmaxf(v00, 0.f); v01 = fmaxf(v01, 0.f);
                v10 = fmaxf(v10, 0.f); v11 = fmaxf(v11, 0.f);
            }
            if (outmode & 1) {
                *(float2*)(Cf32 + (size_t)row0 * N + col)       = make_float2(v00, v01);
                *(float2*)(Cf32 + (size_t)(row0 + 8) * N + col) = make_float2(v10, v11);
            }
            if (outmode & 2) {
                split_store(v00, Shi, Slo, (size_t)row0 * N + col);
                split_store(v01, Shi, Slo, (size_t)row0 * N + col + 1);
                split_store(v10, Shi, Slo, (size_t)(row0 + 8) * N + col);
                split_store(v11, Shi, Slo, (size_t)(row0 + 8) * N + col + 1);
            }
        }
    }
}

__global__ void gemm_bf16_kernel(int a_code, size_t w_off, const float* __restrict__ bias,
                                 int N, int K, int act, int outmode, int c_code, int s_code)
{
    float* Cf32 = (outmode & 1) ? scratch(c_code) : nullptr;
    bf16* Shi = (outmode & 2) ? split_hi_w(s_code) : nullptr;
    bf16* Slo = (outmode & 2) ? split_lo_w(s_code) : nullptr;
    gemm_bf16_core(split_hi(a_code), split_lo(a_code),
                   s_W_hi + w_off, s_W_lo + w_off, bias,
                   Cf32, Shi, Slo, N, K,
                   blockIdx.y * CTM, blockIdx.x * CTN, act, outmode);
}

// Fused QKV: virtual cols 3*768; each 64-col block belongs to one matrix
__global__ void gemm_qkv_bf16_kernel(size_t offq, size_t offk, size_t offv,
                                     const float* __restrict__ bq,
                                     const float* __restrict__ bk,
                                     const float* __restrict__ bv)
{
    const int gcol = blockIdx.x * CTN;
    const int mat  = gcol / DM_;
    const int colBase = gcol - mat * DM_;
    size_t w_off      = (mat == 0) ? offq : (mat == 1) ? offk : offv;
    const float* bias = (mat == 0) ? bq   : (mat == 1) ? bk   : bv;
    float* C          = (mat == 0) ? g_q  : (mat == 1) ? g_k  : g_v;
    const int act     = (mat < 2) ? 1 : 0;
    gemm_bf16_core(s_h_hi, s_h_lo, s_W_hi + w_off, s_W_lo + w_off, bias,
                   C, nullptr, nullptr, DM_, DM_,
                   blockIdx.y * CTM, colBase, act, 1);
}

// ---------------------------------------------------------------------------
// Causal linear attention (fp32 in, bf16-split out). Grid (4, 32); 256 thr.
// ---------------------------------------------------------------------------
#define CHUNK 20
#define ALD   193

__global__ void attn_kernel()
{
    __shared__ float Qs [CHUNK][ALD];
    __shared__ float KVs[CHUNK][ALD];
    __shared__ float Asc[CHUNK][T_];
    __shared__ float inv[CHUNK];

    const int chunk = blockIdx.x;      // 0..3
    const int bh    = blockIdx.y;      // 0..31
    const int b  = bh >> 2;
    const int h  = bh & 3;
    const int t0 = chunk * CHUNK;
    const int tid = threadIdx.x;

    for (int i = tid; i < CHUNK * DH_; i += 256) {
        int tl = i / DH_, d = i - tl * DH_;
        Qs[tl][d] = g_q[(size_t)((t0 + tl) * BS_ + b) * DM_ + h * DH_ + d];
    }
    __syncthreads();

    for (int tt = 0; tt <= chunk; tt++) {
        const int tauBase = tt * CHUNK;
        for (int i = tid; i < CHUNK * DH_; i += 256) {
            int j = i / DH_, d = i - j * DH_;
            KVs[j][d] = g_k[(size_t)((tauBase + j) * BS_ + b) * DM_ + h * DH_ + d];
        }
        __syncthreads();

        for (int p = tid; p < CHUNK * CHUNK; p += 256) {
            int tl = p / CHUNK, tj = p - tl * CHUNK;
            float s = 0.0f;
            if (tauBase + tj <= t0 + tl) {
                #pragma unroll 8
                for (int d = 0; d < DH_; d++) s += Qs[tl][d] * KVs[tj][d];
            }
            Asc[tl][tauBase + tj] = s;
        }
        __syncthreads();
    }

    const int width = (chunk + 1) * CHUNK;
    if (tid < CHUNK) {
        float s = 0.0f;
        for (int tau = 0; tau < width; tau++) s += Asc[tid][tau];
        inv[tid] = 1.0f / (s + EPS_ATT);
    }
    __syncthreads();

    float acc[(CHUNK * DH_ + 255) / 256] = {};
    for (int tt = 0; tt <= chunk; tt++) {
        const int tauBase = tt * CHUNK;
        for (int i = tid; i < CHUNK * DH_; i += 256) {
            int j = i / DH_, d = i - j * DH_;
            KVs[j][d] = g_v[(size_t)((tauBase + j) * BS_ + b) * DM_ + h * DH_ + d];
        }
        __syncthreads();

        #pragma unroll
        for (int it = 0; it < (CHUNK * DH_ + 255) / 256; it++) {
            int idx = tid + it * 256;
            int tl = idx / DH_, d = idx - tl * DH_;
            float a = 0.0f;
            #pragma unroll
            for (int j = 0; j < CHUNK; j++) a += Asc[tl][tauBase + j] * KVs[j][d];
            acc[it] += a;
        }
        __syncthreads();
    }

    #pragma unroll
    for (int it = 0; it < (CHUNK * DH_ + 255) / 256; it++) {
        int idx = tid + it * 256;
        int tl = idx / DH_, d = idx - tl * DH_;
        float v = acc[it] * inv[tl];
        split_store(v, s_att_hi, s_att_lo,
                    (size_t)((t0 + tl) * BS_ + b) * DM_ + h * DH_ + d);
    }
}

// ---------------------------------------------------------------------------
// LayerNorm(x + y) — writes fp32 out + optional bf16 split
// ---------------------------------------------------------------------------
__device__ __forceinline__ float block_sum_256(float val)
{
    __shared__ float sh[8];
    const int lane = threadIdx.x & 31;
    const int w    = threadIdx.x >> 5;
    #pragma unroll
    for (int o = 16; o > 0; o >>= 1) val += __shfl_down_sync(0xffffffffu, val, o);
    if (lane == 0) sh[w] = val;
    __syncthreads();
    if (w == 0) {
        float r = (lane < 8) ? sh[lane] : 0.0f;
        #pragma unroll
        for (int o = 4; o > 0; o >>= 1) r += __shfl_down_sync(0xffffffffu, r, o);
        if (lane == 0) sh[0] = r;
    }
    __syncthreads();
    float res = sh[0];
    __syncthreads();
    return res;
}

__global__ void ln_residual_kernel(int x_code, int y_code,
                                   const float* __restrict__ g, const float* __restrict__ bt,
                                   int out_code, int s_code)
{
    const float* x  = scratch(x_code);
    const float* yv = scratch(y_code);
    float* out      = scratch(out_code);
    bf16* shi = split_hi_w(s_code);
    bf16* slo = split_lo_w(s_code);

    const int row = blockIdx.x;
    const int tid = threadIdx.x;
    const size_t base = (size_t)row * DM_;

    float v0 = x[base + tid]       + yv[base + tid];
    float v1 = x[base + tid + 256] + yv[base + tid + 256];
    float v2 = x[base + tid + 512] + yv[base + tid + 512];

    float mean = block_sum_256(v0 + v1 + v2) * (1.0f / (float)DM_);
    float d0 = v0 - mean, d1 = v1 - mean, d2 = v2 - mean;
    float var = block_sum_256(d0*d0 + d1*d1 + d2*d2) * (1.0f / (float)DM_);
    float rstd = rsqrtf(var + EPS_LN);

    float o0 = d0 * rstd * g[tid]       + bt[tid];
    float o1 = d1 * rstd * g[tid + 256] + bt[tid + 256];
    float o2 = d2 * rstd * g[tid + 512] + bt[tid + 512];

    out[base + tid]       = o0;
    out[base + tid + 256] = o1;
    out[base + tid + 512] = o2;
    split_store(o0, shi, slo, base + tid);
    split_store(o1, shi, slo, base + tid + 256);
    split_store(o2, shi, slo, base + tid + 512);
}

// ---------------------------------------------------------------------------
// Final: gather selected rows, final LN, emit mu || logvar
// ---------------------------------------------------------------------------
__global__ void gather_kernel(const int* __restrict__ act_ts,
                              const float* __restrict__ g, const float* __restrict__ bt,
                              float* __restrict__ out)
{
    const int ba = blockIdx.x;            // b*A + a
    const int b  = ba / A_;
    int t = act_ts[ba] - 1;
    if (t < 0) t = 0;
    const int row = t * BS_ + b;
    const int tid = threadIdx.x;
    const size_t base = (size_t)row * DM_;

    float v0 = g_h[base + tid];
    float v1 = g_h[base + tid + 256];
    float v2 = g_h[base + tid + 512];

    float mean = block_sum_256(v0 + v1 + v2) * (1.0f / (float)DM_);
    float d0 = v0 - mean, d1 = v1 - mean, d2 = v2 - mean;
    float var = block_sum_256(d0*d0 + d1*d1 + d2*d2) * (1.0f / (float)DM_);
    float rstd = rsqrtf(var + EPS_LN);

    out[(size_t)ba * LATENT_ + tid]                      = d0 * rstd * g[tid]       + bt[tid];
    out[(size_t)BS_ * A_ * LATENT_ + ba * LATENT_ + tid] = d1 * rstd * g[tid + 256] + bt[tid + 256];
}

// ---------------------------------------------------------------------------
// Host orchestration: kernel launches ONLY (graph-capture safe)
// ---------------------------------------------------------------------------
extern "C" void kernel_launch(void* const* d_in, const int* in_sizes, int n_in,
                              void* d_out, int out_size)
{
    const float* x    = (const float*)d_in[0];
    const int*   y    = (const int*)  d_in[1];
    const int*   ind  = (const int*)  d_in[2];
    const int*   ats  = (const int*)  d_in[3];
    const float* skW  = (const float*)d_in[4];
    const float* skb  = (const float*)d_in[5];
    const float* muQ  = (const float*)d_in[6];
    const float* sgQ  = (const float*)d_in[7];
    const float* Wq   = (const float*)d_in[8];
    const float* bq   = (const float*)d_in[9];
    const float* Wk   = (const float*)d_in[10];
    const float* bk   = (const float*)d_in[11];
    const float* Wv   = (const float*)d_in[12];
    const float* bv   = (const float*)d_in[13];
    const float* Wo   = (const float*)d_in[14];
    const float* bo   = (const float*)d_in[15];
    const float* W1   = (const float*)d_in[16];
    const float* b1   = (const float*)d_in[17];
    const float* W2   = (const float*)d_in[18];
    const float* b2   = (const float*)d_in[19];
    const float* l1g  = (const float*)d_in[20];
    const float* l1b  = (const float*)d_in[21];
    const float* l2g  = (const float*)d_in[22];
    const float* l2b  = (const float*)d_in[23];
    const float* lfg  = (const float*)d_in[24];
    const float* lfb  = (const float*)d_in[25];
    float* out = (float*)d_out;

    split_weights_kernel<<<(unsigned)((TOTALW / 4 + 255) / 256), 256>>>(Wq, Wk, Wv, Wo, W1, W2);
    build_h0_kernel<<<ROWS_, 256>>>(x, y, ind, skW, skb, muQ, sgQ);

    const dim3 gQKV(3 * DM_ / CTN, ROWS_ / CTM);   // 36 x 20 = 720
    const dim3 g768(DM_ / CTN, ROWS_ / CTM);       // 12 x 20 = 240
    const dim3 g1024(FF_ / CTN, ROWS_ / CTM);      // 16 x 20 = 320
    const dim3 gAttn(4, BS_ * H_);

    const size_t szAttL = (size_t)DM_ * DM_;   // 589824 per layer
    const size_t szFFL  = (size_t)DM_ * FF_;   // 786432 per layer

    for (int l = 0; l < L_; l++) {
        gemm_qkv_bf16_kernel<<<gQKV, 256>>>(OFF_WQ + l * szAttL,
                                            OFF_WK + l * szAttL,
                                            OFF_WV + l * szAttL,
                                            bq + l * DM_, bk + l * DM_, bv + l * DM_);
        attn_kernel<<<gAttn, 256>>>();
        // O projection -> g_q (fp32 tmp)
        gemm_bf16_kernel<<<g768, 256>>>(SPL_ATT, OFF_WO + l * szAttL, bo + l * DM_,
                                        DM_, DM_, 0, 1, BUF_Q, 0);
        ln_residual_kernel<<<ROWS_, 256>>>(BUF_H, BUF_Q, l1g + l * DM_, l1b + l * DM_,
                                           BUF_H1, SPL_H1);
        // FF1 -> split only
        gemm_bf16_kernel<<<g1024, 256>>>(SPL_H1, OFF_W1 + l * szFFL, b1 + l * FF_,
                                         FF_, DM_, 2, 2, 0, SPL_FF);
        // FF2 -> g_q (fp32 tmp)
        gemm_bf16_kernel<<<g768, 256>>>(SPL_FF, OFF_W2 + l * szFFL, b2 + l * DM_,
                                        DM_, FF_, 0, 1, BUF_Q, 0);
        ln_residual_kernel<<<ROWS_, 256>>>(BUF_H1, BUF_Q, l2g + l * DM_, l2b + l * DM_,
                                           BUF_H, SPL_H);
    }

    gather_kernel<<<BS_ * A_, 256>>>(ats, lfg, lfb, out);
}

// round 11
// speedup vs baseline: 2.8883x; 1.0418x over previous
#include <cuda_runtime.h>
#include <cuda_bf16.h>
#include <math.h>
#include <stdint.h>

// Problem constants
#define T_      80
#define BS_     8
#define DM_     768
#define H_      4
#define DH_     192
#define FF_     1024
#define L_      4
#define LATENT_ 256
#define ROWS_   (T_ * BS_)      // 640
#define NJF_    150
#define A_      6

#define EPS_ATT 1e-6f
#define EPS_LN  1e-5f

typedef __nv_bfloat16 bf16;

// ---------------------------------------------------------------------------
// Scratch (device globals only; no cudaMalloc anywhere)
// ---------------------------------------------------------------------------
__device__ __align__(16) float g_h [ROWS_ * DM_];
__device__ __align__(16) float g_h1[ROWS_ * DM_];
__device__ __align__(16) float g_q [ROWS_ * DM_];   // fp32 GEMM temp (O-proj / FF2)

#define BUF_H   0
#define BUF_H1  1
#define BUF_Q   2

__device__ __forceinline__ float* scratch(int code)
{
    switch (code) {
        case BUF_H:  return g_h;
        case BUF_H1: return g_h1;
        default:     return g_q;
    }
}

// bf16 hi/lo split activations
__device__ __align__(16) bf16 s_h_hi  [ROWS_ * DM_];
__device__ __align__(16) bf16 s_h_lo  [ROWS_ * DM_];
__device__ __align__(16) bf16 s_att_hi[ROWS_ * DM_];
__device__ __align__(16) bf16 s_att_lo[ROWS_ * DM_];
__device__ __align__(16) bf16 s_h1_hi [ROWS_ * DM_];
__device__ __align__(16) bf16 s_h1_lo [ROWS_ * DM_];
__device__ __align__(16) bf16 s_ff_hi [ROWS_ * FF_];
__device__ __align__(16) bf16 s_ff_lo [ROWS_ * FF_];
__device__ __align__(16) bf16 s_q_hi  [ROWS_ * DM_];
__device__ __align__(16) bf16 s_q_lo  [ROWS_ * DM_];
__device__ __align__(16) bf16 s_k_hi  [ROWS_ * DM_];
__device__ __align__(16) bf16 s_k_lo  [ROWS_ * DM_];
__device__ __align__(16) bf16 s_v_hi  [ROWS_ * DM_];
__device__ __align__(16) bf16 s_v_lo  [ROWS_ * DM_];

#define SPL_H   0
#define SPL_ATT 1
#define SPL_H1  2
#define SPL_FF  3

__device__ __forceinline__ const bf16* split_hi(int c)
{
    switch (c) { case SPL_H: return s_h_hi; case SPL_ATT: return s_att_hi;
                 case SPL_H1: return s_h1_hi; default: return s_ff_hi; }
}
__device__ __forceinline__ const bf16* split_lo(int c)
{
    switch (c) { case SPL_H: return s_h_lo; case SPL_ATT: return s_att_lo;
                 case SPL_H1: return s_h1_lo; default: return s_ff_lo; }
}
__device__ __forceinline__ bf16* split_hi_w(int c)
{
    switch (c) { case SPL_H: return s_h_hi; case SPL_ATT: return s_att_hi;
                 case SPL_H1: return s_h1_hi; default: return s_ff_hi; }
}
__device__ __forceinline__ bf16* split_lo_w(int c)
{
    switch (c) { case SPL_H: return s_h_lo; case SPL_ATT: return s_att_lo;
                 case SPL_H1: return s_h1_lo; default: return s_ff_lo; }
}

__device__ __forceinline__ void split_store(float v, bf16* hi, bf16* lo, size_t idx)
{
    bf16 h = __float2bfloat16_rn(v);
    hi[idx] = h;
    lo[idx] = __float2bfloat16_rn(v - __bfloat162float(h));
}

// bf16 hi/lo split weights, one big pool each
#define SZW_ATT (L_ * DM_ * DM_)
#define SZW_FF  (L_ * DM_ * FF_)
#define OFF_WQ  ((size_t)0)
#define OFF_WK  ((size_t)SZW_ATT)
#define OFF_WV  ((size_t)(2 * SZW_ATT))
#define OFF_WO  ((size_t)(3 * SZW_ATT))
#define OFF_W1  ((size_t)(4 * SZW_ATT))
#define OFF_W2  ((size_t)(4 * SZW_ATT) + SZW_FF)
#define TOTALW  ((size_t)(4 * SZW_ATT) + 2 * (size_t)SZW_FF)

__device__ __align__(16) bf16 s_W_hi[TOTALW];
__device__ __align__(16) bf16 s_W_lo[TOTALW];

// ---------------------------------------------------------------------------
// Weight splitter
// ---------------------------------------------------------------------------
__global__ void split_weights_kernel(const float* __restrict__ Wq, const float* __restrict__ Wk,
                                     const float* __restrict__ Wv, const float* __restrict__ Wo,
                                     const float* __restrict__ W1, const float* __restrict__ W2)
{
    size_t i4 = ((size_t)blockIdx.x * blockDim.x + threadIdx.x) * 4;
    if (i4 >= TOTALW) return;

    const float* src;
    size_t rel;
    if (i4 < OFF_W1) {
        size_t seg = i4 / (size_t)SZW_ATT;
        rel = i4 - seg * (size_t)SZW_ATT;
        src = (seg == 0) ? Wq : (seg == 1) ? Wk : (seg == 2) ? Wv : Wo;
    } else if (i4 < OFF_W2) {
        src = W1; rel = i4 - OFF_W1;
    } else {
        src = W2; rel = i4 - OFF_W2;
    }

    float4 x = *(const float4*)(src + rel);
    const float xs[4] = {x.x, x.y, x.z, x.w};
    #pragma unroll
    for (int j = 0; j < 4; j++)
        split_store(xs[j], s_W_hi, s_W_lo, i4 + j);
}

// ---------------------------------------------------------------------------
// h0: skeleton embedding + query gathers + PE; writes fp32 + bf16 split
// ---------------------------------------------------------------------------
__global__ void build_h0_kernel(const float* __restrict__ x,
                                const int*   __restrict__ y,
                                const int*   __restrict__ ind_map,
                                const float* __restrict__ skW,
                                const float* __restrict__ skb,
                                const float* __restrict__ muQ,
                                const float* __restrict__ sgQ)
{
    const int r = blockIdx.x;
    const int t = r / BS_;
    const int b = r - t * BS_;
    const int tid = threadIdx.x;

    __shared__ float xrow[NJF_];
    if (tid < NJF_) xrow[tid] = x[(size_t)b * NJF_ * T_ + tid * T_ + t];
    __syncthreads();

    const int a   = ind_map[t * BS_ + b];
    const int cls = y[b * A_ + a];
    const int start = (t == 0) ? 0 : (t + 2);

    const float div = expf(-(logf(10000.0f) / (float)LATENT_) * (float)(tid & ~1));
    const bool  odd = (tid & 1);

    float base0 = muQ[cls * LATENT_ + tid];
    float base1 = sgQ[cls * LATENT_ + tid];
    float acc = skb[tid];
    #pragma unroll 5
    for (int jf = 0; jf < NJF_; jf++) acc += xrow[jf] * skW[jf * LATENT_ + tid];

    const size_t base = (size_t)r * DM_;
    float v0, v1, v2;
    { float ang = (float)(start + 0) * div; v0 = base0 + (odd ? cosf(ang) : sinf(ang)); }
    { float ang = (float)(start + 1) * div; v1 = base1 + (odd ? cosf(ang) : sinf(ang)); }
    { float ang = (float)(start + 2) * div; v2 = acc   + (odd ? cosf(ang) : sinf(ang)); }

    g_h[base + tid]             = v0;
    g_h[base + tid + LATENT_]   = v1;
    g_h[base + tid + 2*LATENT_] = v2;
    split_store(v0, s_h_hi, s_h_lo, base + tid);
    split_store(v1, s_h_hi, s_h_lo, base + tid + LATENT_);
    split_store(v2, s_h_hi, s_h_lo, base + tid + 2*LATENT_);
}

// ---------------------------------------------------------------------------
// bf16 2-term split tensor-core GEMM (m16n8k16 + ldmatrix)
// ---------------------------------------------------------------------------
#define CTM 32
#define CTN 64
#define CTK 32
#define LDA_ 40
#define LDB_ 72

__device__ __forceinline__ uint32_t smem_u32(const void* p)
{
    return (uint32_t)__cvta_generic_to_shared(p);
}

__device__ __forceinline__ void ldm_x4(uint32_t* r, uint32_t addr)
{
    asm volatile("ldmatrix.sync.aligned.m8n8.x4.shared.b16 {%0,%1,%2,%3}, [%4];"
                 : "=r"(r[0]), "=r"(r[1]), "=r"(r[2]), "=r"(r[3]) : "r"(addr));
}
__device__ __forceinline__ void ldm_x4_t(uint32_t* r, uint32_t addr)
{
    asm volatile("ldmatrix.sync.aligned.m8n8.x4.trans.shared.b16 {%0,%1,%2,%3}, [%4];"
                 : "=r"(r[0]), "=r"(r[1]), "=r"(r[2]), "=r"(r[3]) : "r"(addr));
}
__device__ __forceinline__ void mma_bf16(float4& c, const uint32_t* a, uint32_t b0, uint32_t b1)
{
    asm volatile(
        "mma.sync.aligned.m16n8k16.row.col.f32.bf16.bf16.f32 "
        "{%0,%1,%2,%3},{%4,%5,%6,%7},{%8,%9},{%0,%1,%2,%3};"
        : "+f"(c.x), "+f"(c.y), "+f"(c.z), "+f"(c.w)
        : "r"(a[0]), "r"(a[1]), "r"(a[2]), "r"(a[3]), "r"(b0), "r"(b1));
}

__device__ __forceinline__ void gemm_bf16_core(
    const bf16* __restrict__ Ahi, const bf16* __restrict__ Alo,
    const bf16* __restrict__ Bhi, const bf16* __restrict__ Blo,
    const float* __restrict__ bias,
    float* Cf32, bf16* Shi, bf16* Slo,
    int N, int K, int rowBase, int colBase, int act, int outmode)
{
    __shared__ __align__(16) bf16 sA[2][2][CTM * LDA_];
    __shared__ __align__(16) bf16 sB[2][2][CTK * LDB_];
    __shared__ float red[2048];

    const int tid  = threadIdx.x;
    const int lane = tid & 31;
    const int wid  = tid >> 5;
    const int warp_m = wid & 1;
    const int warp_n = (wid >> 1) & 1;
    const int warp_k = wid >> 2;

    const int matA = tid >> 7;
    const int arem = tid & 127;
    const int ar = arem >> 2, ac = arem & 3;
    const int br = tid >> 3,  bc = tid & 7;

    const bf16* Asel = matA ? Alo : Ahi;
    const bf16* Agm  = Asel + (size_t)(rowBase + ar) * K + ac * 8;
    const bf16* Bgm_hi = Bhi + (size_t)br * N + colBase + bc * 8;
    const bf16* Bgm_lo = Blo + (size_t)br * N + colBase + bc * 8;

    bf16* AsmDst0 = &sA[0][matA][ar * LDA_ + ac * 8];
    bf16* AsmDst1 = &sA[1][matA][ar * LDA_ + ac * 8];
    bf16* BsmH0 = &sB[0][0][br * LDB_ + bc * 8];
    bf16* BsmH1 = &sB[1][0][br * LDB_ + bc * 8];
    bf16* BsmL0 = &sB[0][1][br * LDB_ + bc * 8];
    bf16* BsmL1 = &sB[1][1][br * LDB_ + bc * 8];

    const int aoff  = (warp_m * 16 + (lane & 15)) * LDA_ + warp_k * 16 + (lane >> 4) * 8;
    const int boff0 = (warp_k * 16 + (lane & 15)) * LDB_ + warp_n * 32 + (lane >> 4) * 8;
    const int boff1 = boff0 + 16;

    float4 acc[4] = {{0,0,0,0},{0,0,0,0},{0,0,0,0},{0,0,0,0}};

    const int KT = K / CTK;

    {
        uint4 pa = *(const uint4*)Agm;
        uint4 pb0 = *(const uint4*)Bgm_hi;
        uint4 pb1 = *(const uint4*)Bgm_lo;
        *(uint4*)AsmDst0 = pa;
        *(uint4*)BsmH0 = pb0;
        *(uint4*)BsmL0 = pb1;
    }
    __syncthreads();

    int buf = 0;
    for (int kt = 0; kt < KT; kt++) {
        uint4 pa, pb0, pb1;
        const bool more = (kt + 1 < KT);
        if (more) {
            pa  = *(const uint4*)(Agm + (kt + 1) * CTK);
            pb0 = *(const uint4*)(Bgm_hi + (size_t)(kt + 1) * CTK * N);
            pb1 = *(const uint4*)(Bgm_lo + (size_t)(kt + 1) * CTK * N);
        }

        uint32_t ah[4], al[4], bh0[4], bh1[4], bl0[4], bl1[4];
        ldm_x4  (ah,  smem_u32(&sA[buf][0][aoff]));
        ldm_x4  (al,  smem_u32(&sA[buf][1][aoff]));
        ldm_x4_t(bh0, smem_u32(&sB[buf][0][boff0]));
        ldm_x4_t(bh1, smem_u32(&sB[buf][0][boff1]));
        ldm_x4_t(bl0, smem_u32(&sB[buf][1][boff0]));
        ldm_x4_t(bl1, smem_u32(&sB[buf][1][boff1]));

        mma_bf16(acc[0], ah, bh0[0], bh0[1]);
        mma_bf16(acc[0], ah, bl0[0], bl0[1]);
        mma_bf16(acc[0], al, bh0[0], bh0[1]);

        mma_bf16(acc[1], ah, bh0[2], bh0[3]);
        mma_bf16(acc[1], ah, bl0[2], bl0[3]);
        mma_bf16(acc[1], al, bh0[2], bh0[3]);

        mma_bf16(acc[2], ah, bh1[0], bh1[1]);
        mma_bf16(acc[2], ah, bl1[0], bl1[1]);
        mma_bf16(acc[2], al, bh1[0], bh1[1]);

        mma_bf16(acc[3], ah, bh1[2], bh1[3]);
        mma_bf16(acc[3], ah, bl1[2], bl1[3]);
        mma_bf16(acc[3], al, bh1[2], bh1[3]);

        if (more) {
            if (buf == 0) { *(uint4*)AsmDst1 = pa; *(uint4*)BsmH1 = pb0; *(uint4*)BsmL1 = pb1; }
            else          { *(uint4*)AsmDst0 = pa; *(uint4*)BsmH0 = pb0; *(uint4*)BsmL0 = pb1; }
        }
        __syncthreads();
        buf ^= 1;
    }

    float* af = reinterpret_cast<float*>(acc);
    if (warp_k == 1) {
        int base = (wid - 4) * 32 + lane;
        #pragma unroll
        for (int j = 0; j < 16; j++) red[j * 128 + base] = af[j];
    }
    __syncthreads();
    if (warp_k == 0) {
        int base = wid * 32 + lane;
        #pragma unroll
        for (int j = 0; j < 16; j++) af[j] += red[j * 128 + base];

        const int row0 = rowBase + warp_m * 16 + (lane >> 2);
        #pragma unroll
        for (int nt = 0; nt < 4; nt++) {
            const int col = colBase + warp_n * 32 + nt * 8 + 2 * (lane & 3);
            float2 bb = *(const float2*)(bias + col);
            float v00 = acc[nt].x + bb.x, v01 = acc[nt].y + bb.y;
            float v10 = acc[nt].z + bb.x, v11 = acc[nt].w + bb.y;
            if (act == 1) {
                v00 = (v00 > 0.f) ? (v00 + 1.f) : expf(v00);
                v01 = (v01 > 0.f) ? (v01 + 1.f) : expf(v01);
                v10 = (v10 > 0.f) ? (v10 + 1.f) : expf(v10);
                v11 = (v11 > 0.f) ? (v11 + 1.f) : expf(v11);
            } else if (act == 2) {
                v00 = fmaxf(v00, 0.f); v01 = fmaxf(v01, 0.f);
                v10 = fmaxf(v10, 0.f); v11 = fmaxf(v11, 0.f);
            }
            if (outmode & 1) {
                *(float2*)(Cf32 + (size_t)row0 * N + col)       = make_float2(v00, v01);
                *(float2*)(Cf32 + (size_t)(row0 + 8) * N + col) = make_float2(v10, v11);
            }
            if (outmode & 2) {
                split_store(v00, Shi, Slo, (size_t)row0 * N + col);
                split_store(v01, Shi, Slo, (size_t)row0 * N + col + 1);
                split_store(v10, Shi, Slo, (size_t)(row0 + 8) * N + col);
                split_store(v11, Shi, Slo, (size_t)(row0 + 8) * N + col + 1);
            }
        }
    }
}

__global__ void gemm_bf16_kernel(int a_code, size_t w_off, const float* __restrict__ bias,
                                 int N, int K, int act, int outmode, int c_code, int s_code)
{
    float* Cf32 = (outmode & 1) ? scratch(c_code) : nullptr;
    bf16* Shi = (outmode & 2) ? split_hi_w(s_code) : nullptr;
    bf16* Slo = (outmode & 2) ? split_lo_w(s_code) : nullptr;
    gemm_bf16_core(split_hi(a_code), split_lo(a_code),
                   s_W_hi + w_off, s_W_lo + w_off, bias,
                   Cf32, Shi, Slo, N, K,
                   blockIdx.y * CTM, blockIdx.x * CTN, act, outmode);
}

// Fused QKV: writes Q,K,V as bf16 splits (no fp32)
__global__ void gemm_qkv_bf16_kernel(size_t offq, size_t offk, size_t offv,
                                     const float* __restrict__ bq,
                                     const float* __restrict__ bk,
                                     const float* __restrict__ bv)
{
    const int gcol = blockIdx.x * CTN;
    const int mat  = gcol / DM_;
    const int colBase = gcol - mat * DM_;
    size_t w_off      = (mat == 0) ? offq : (mat == 1) ? offk : offv;
    const float* bias = (mat == 0) ? bq   : (mat == 1) ? bk   : bv;
    bf16* shi         = (mat == 0) ? s_q_hi : (mat == 1) ? s_k_hi : s_v_hi;
    bf16* slo         = (mat == 0) ? s_q_lo : (mat == 1) ? s_k_lo : s_v_lo;
    const int act     = (mat < 2) ? 1 : 0;
    gemm_bf16_core(s_h_hi, s_h_lo, s_W_hi + w_off, s_W_lo + w_off, bias,
                   nullptr, shi, slo, DM_, DM_,
                   blockIdx.y * CTM, colBase, act, 2);
}

// ---------------------------------------------------------------------------
// Tensor-core causal linear attention. One block per (b,h), 256 threads.
// Phase A: S = Q K^T (split bf16, 3-term), causal mask, rowsum -> inv.
// Phase C: O = (S V) * inv, written as split bf16 to s_att.
// ---------------------------------------------------------------------------
#define AQLD 24     // QK chunk row stride (16 + 8 pad)
#define SLD  88     // S row stride (80 + 8 pad)
#define VLD  200    // V chunk row stride (192 + 8 pad)

__device__ __forceinline__ void split2smem(float v, bf16* hi, bf16* lo, int idx)
{
    bf16 h = __float2bfloat16_rn(v);
    hi[idx] = h;
    lo[idx] = __float2bfloat16_rn(v - __bfloat162float(h));
}

__global__ void attn_mma_kernel()
{
    __shared__ __align__(16) bf16 sSh[T_ * SLD];          // 14080 B
    __shared__ __align__(16) bf16 sSl[T_ * SLD];          // 14080 B
    __shared__ __align__(16) bf16 stage[4 * T_ * AQLD];   // 15360 B (also V: 2*16*VLD=6400 elems)
    __shared__ float inv_s[T_];

    const int bh = blockIdx.x;
    const int b = bh >> 2, h = bh & 3;
    const int tid = threadIdx.x, lane = tid & 31, wid = tid >> 5;
    const int g = lane >> 2, tq = lane & 3;

    // ---------------- Phase A: scores ----------------
    float4 accA[4][2];
    #pragma unroll
    for (int j = 0; j < 4; j++) { accA[j][0] = make_float4(0,0,0,0); accA[j][1] = make_float4(0,0,0,0); }

    for (int kc = 0; kc < 12; kc++) {
        __syncthreads();
        for (int i = tid; i < 640; i += 256) {
            int plane = i / 160, rem = i - plane * 160;
            int t = rem >> 1, cg = (rem & 1) << 3;
            const bf16* src = (plane == 0) ? s_q_hi : (plane == 1) ? s_q_lo
                            : (plane == 2) ? s_k_hi : s_k_lo;
            *(uint4*)&stage[plane * T_ * AQLD + t * AQLD + cg] =
                *(const uint4*)&src[(size_t)(t * BS_ + b) * DM_ + h * DH_ + kc * 16 + cg];
        }
        __syncthreads();

        #pragma unroll
        for (int j = 0; j < 4; j++) {
            int u = wid + 8 * j;
            if (u < 25) {
                int mi = u / 5, ni = u - mi * 5;
                uint32_t qh[4], ql[4], kh[4], kl[4];
                int aoff = (mi * 16 + (lane & 15)) * AQLD + ((lane >> 4) << 3);
                int koff = (ni * 16 + (lane & 15)) * AQLD + ((lane >> 4) << 3);
                ldm_x4(qh, smem_u32(&stage[0 * T_ * AQLD + aoff]));
                ldm_x4(ql, smem_u32(&stage[1 * T_ * AQLD + aoff]));
                ldm_x4(kh, smem_u32(&stage[2 * T_ * AQLD + koff]));
                ldm_x4(kl, smem_u32(&stage[3 * T_ * AQLD + koff]));
                // K is [tau][d] row-major == B-operand layout directly (no trans)
                mma_bf16(accA[j][0], qh, kh[0], kh[2]);
                mma_bf16(accA[j][0], qh, kl[0], kl[2]);
                mma_bf16(accA[j][0], ql, kh[0], kh[2]);
                mma_bf16(accA[j][1], qh, kh[1], kh[3]);
                mma_bf16(accA[j][1], qh, kl[1], kl[3]);
                mma_bf16(accA[j][1], ql, kh[1], kh[3]);
            }
        }
    }
    __syncthreads();

    // masked split store of S
    #pragma unroll
    for (int j = 0; j < 4; j++) {
        int u = wid + 8 * j;
        if (u < 25) {
            int mi = u / 5, ni = u - mi * 5;
            int r0 = mi * 16 + g, r1 = r0 + 8;
            #pragma unroll
            for (int n8 = 0; n8 < 2; n8++) {
                int c = ni * 16 + n8 * 8 + 2 * tq;
                float4 a = accA[j][n8];
                split2smem((c     <= r0) ? a.x : 0.f, sSh, sSl, r0 * SLD + c);
                split2smem((c + 1 <= r0) ? a.y : 0.f, sSh, sSl, r0 * SLD + c + 1);
                split2smem((c     <= r1) ? a.z : 0.f, sSh, sSl, r1 * SLD + c);
                split2smem((c + 1 <= r1) ? a.w : 0.f, sSh, sSl, r1 * SLD + c + 1);
            }
        }
    }
    __syncthreads();

    if (tid < T_) {
        float s = 0.0f;
        for (int c = 0; c < T_; c++)
            s += __bfloat162float(sSh[tid * SLD + c]) + __bfloat162float(sSl[tid * SLD + c]);
        inv_s[tid] = 1.0f / (s + EPS_ATT);
    }

    // ---------------- Phase C: O = S V ----------------
    float4 accC[8][2];
    #pragma unroll
    for (int j = 0; j < 8; j++) { accC[j][0] = make_float4(0,0,0,0); accC[j][1] = make_float4(0,0,0,0); }

    for (int kc = 0; kc < 5; kc++) {
        __syncthreads();
        for (int i = tid; i < 768; i += 256) {
            int plane = i / 384, rem = i - plane * 384;
            int t = rem / 24, cg = (rem - t * 24) << 3;
            const bf16* src = plane ? s_v_lo : s_v_hi;
            *(uint4*)&stage[plane * 16 * VLD + t * VLD + cg] =
                *(const uint4*)&src[(size_t)((kc * 16 + t) * BS_ + b) * DM_ + h * DH_ + cg];
        }
        __syncthreads();

        #pragma unroll
        for (int j = 0; j < 8; j++) {
            int u = wid + 8 * j;
            if (u < 60) {
                int mi = u / 12, ni = u - mi * 12;
                uint32_t sh[4], sl[4], vh[4], vl[4];
                int aoff = (mi * 16 + (lane & 15)) * SLD + kc * 16 + ((lane >> 4) << 3);
                int boff = (lane & 15) * VLD + ni * 16 + ((lane >> 4) << 3);
                ldm_x4(sh, smem_u32(&sSh[aoff]));
                ldm_x4(sl, smem_u32(&sSl[aoff]));
                ldm_x4_t(vh, smem_u32(&stage[boff]));
                ldm_x4_t(vl, smem_u32(&stage[16 * VLD + boff]));
                mma_bf16(accC[j][0], sh, vh[0], vh[1]);
                mma_bf16(accC[j][0], sh, vl[0], vl[1]);
                mma_bf16(accC[j][0], sl, vh[0], vh[1]);
                mma_bf16(accC[j][1], sh, vh[2], vh[3]);
                mma_bf16(accC[j][1], sh, vl[2], vl[3]);
                mma_bf16(accC[j][1], sl, vh[2], vh[3]);
            }
        }
    }

    // output: scale by inv, split-store to s_att
    #pragma unroll
    for (int j = 0; j < 8; j++) {
        int u = wid + 8 * j;
        if (u < 60) {
            int mi = u / 12, ni = u - mi * 12;
            int r0 = mi * 16 + g, r1 = r0 + 8;
            float i0 = inv_s[r0], i1 = inv_s[r1];
            #pragma unroll
            for (int n8 = 0; n8 < 2; n8++) {
                int d = ni * 16 + n8 * 8 + 2 * tq;
                float4 a = accC[j][n8];
                size_t o0 = (size_t)(r0 * BS_ + b) * DM_ + h * DH_ + d;
                size_t o1 = (size_t)(r1 * BS_ + b) * DM_ + h * DH_ + d;
                split_store(a.x * i0, s_att_hi, s_att_lo, o0);
                split_store(a.y * i0, s_att_hi, s_att_lo, o0 + 1);
                split_store(a.z * i1, s_att_hi, s_att_lo, o1);
                split_store(a.w * i1, s_att_hi, s_att_lo, o1 + 1);
            }
        }
    }
}

// ---------------------------------------------------------------------------
// LayerNorm helpers
// ---------------------------------------------------------------------------
__device__ __forceinline__ float block_sum_256(float val)
{
    __shared__ float sh[8];
    const int lane = threadIdx.x & 31;
    const int w    = threadIdx.x >> 5;
    #pragma unroll
    for (int o = 16; o > 0; o >>= 1) val += __shfl_down_sync(0xffffffffu, val, o);
    if (lane == 0) sh[w] = val;
    __syncthreads();
    if (w == 0) {
        float r = (lane < 8) ? sh[lane] : 0.0f;
        #pragma unroll
        for (int o = 4; o > 0; o >>= 1) r += __shfl_down_sync(0xffffffffu, r, o);
        if (lane == 0) sh[0] = r;
    }
    __syncthreads();
    float res = sh[0];
    __syncthreads();
    return res;
}

__global__ void ln_residual_kernel(int x_code, int y_code,
                                   const float* __restrict__ g, const float* __restrict__ bt,
                                   int out_code, int s_code)
{
    const float* x  = scratch(x_code);
    const float* yv = scratch(y_code);
    float* out      = scratch(out_code);
    bf16* shi = split_hi_w(s_code);
    bf16* slo = split_lo_w(s_code);

    const int row = blockIdx.x;
    const int tid = threadIdx.x;
    const size_t base = (size_t)row * DM_;

    float v0 = x[base + tid]       + yv[base + tid];
    float v1 = x[base + tid + 256] + yv[base + tid + 256];
    float v2 = x[base + tid + 512] + yv[base + tid + 512];

    float mean = block_sum_256(v0 + v1 + v2) * (1.0f / (float)DM_);
    float d0 = v0 - mean, d1 = v1 - mean, d2 = v2 - mean;
    float var = block_sum_256(d0*d0 + d1*d1 + d2*d2) * (1.0f / (float)DM_);
    float rstd = rsqrtf(var + EPS_LN);

    float o0 = d0 * rstd * g[tid]       + bt[tid];
    float o1 = d1 * rstd * g[tid + 256] + bt[tid + 256];
    float o2 = d2 * rstd * g[tid + 512] + bt[tid + 512];

    out[base + tid]       = o0;
    out[base + tid + 256] = o1;
    out[base + tid + 512] = o2;
    split_store(o0, shi, slo, base + tid);
    split_store(o1, shi, slo, base + tid + 256);
    split_store(o2, shi, slo, base + tid + 512);
}

// ---------------------------------------------------------------------------
// Final: gather selected rows, final LN, emit mu || logvar
// ---------------------------------------------------------------------------
__global__ void gather_kernel(const int* __restrict__ act_ts,
                              const float* __restrict__ g, const float* __restrict__ bt,
                              float* __restrict__ out)
{
    const int ba = blockIdx.x;
    const int b  = ba / A_;
    int t = act_ts[ba] - 1;
    if (t < 0) t = 0;
    const int row = t * BS_ + b;
    const int tid = threadIdx.x;
    const size_t base = (size_t)row * DM_;

    float v0 = g_h[base + tid];
    float v1 = g_h[base + tid + 256];
    float v2 = g_h[base + tid + 512];

    float mean = block_sum_256(v0 + v1 + v2) * (1.0f / (float)DM_);
    float d0 = v0 - mean, d1 = v1 - mean, d2 = v2 - mean;
    float var = block_sum_256(d0*d0 + d1*d1 + d2*d2) * (1.0f / (float)DM_);
    float rstd = rsqrtf(var + EPS_LN);

    out[(size_t)ba * LATENT_ + tid]                      = d0 * rstd * g[tid]       + bt[tid];
    out[(size_t)BS_ * A_ * LATENT_ + ba * LATENT_ + tid] = d1 * rstd * g[tid + 256] + bt[tid + 256];
}

// ---------------------------------------------------------------------------
// Host orchestration: kernel launches ONLY (graph-capture safe)
// ---------------------------------------------------------------------------
extern "C" void kernel_launch(void* const* d_in, const int* in_sizes, int n_in,
                              void* d_out, int out_size)
{
    const float* x    = (const float*)d_in[0];
    const int*   y    = (const int*)  d_in[1];
    const int*   ind  = (const int*)  d_in[2];
    const int*   ats  = (const int*)  d_in[3];
    const float* skW  = (const float*)d_in[4];
    const float* skb  = (const float*)d_in[5];
    const float* muQ  = (const float*)d_in[6];
    const float* sgQ  = (const float*)d_in[7];
    const float* Wq   = (const float*)d_in[8];
    const float* bq   = (const float*)d_in[9];
    const float* Wk   = (const float*)d_in[10];
    const float* bk   = (const float*)d_in[11];
    const float* Wv   = (const float*)d_in[12];
    const float* bv   = (const float*)d_in[13];
    const float* Wo   = (const float*)d_in[14];
    const float* bo   = (const float*)d_in[15];
    const float* W1   = (const float*)d_in[16];
    const float* b1   = (const float*)d_in[17];
    const float* W2   = (const float*)d_in[18];
    const float* b2   = (const float*)d_in[19];
    const float* l1g  = (const float*)d_in[20];
    const float* l1b  = (const float*)d_in[21];
    const float* l2g  = (const float*)d_in[22];
    const float* l2b  = (const float*)d_in[23];
    const float* lfg  = (const float*)d_in[24];
    const float* lfb  = (const float*)d_in[25];
    float* out = (float*)d_out;

    split_weights_kernel<<<(unsigned)((TOTALW / 4 + 255) / 256), 256>>>(Wq, Wk, Wv, Wo, W1, W2);
    build_h0_kernel<<<ROWS_, 256>>>(x, y, ind, skW, skb, muQ, sgQ);

    const dim3 gQKV(3 * DM_ / CTN, ROWS_ / CTM);   // 36 x 20
    const dim3 g768(DM_ / CTN, ROWS_ / CTM);       // 12 x 20
    const dim3 g1024(FF_ / CTN, ROWS_ / CTM);      // 16 x 20

    const size_t szAttL = (size_t)DM_ * DM_;
    const size_t szFFL  = (size_t)DM_ * FF_;

    for (int l = 0; l < L_; l++) {
        gemm_qkv_bf16_kernel<<<gQKV, 256>>>(OFF_WQ + l * szAttL,
                                            OFF_WK + l * szAttL,
                                            OFF_WV + l * szAttL,
                                            bq + l * DM_, bk + l * DM_, bv + l * DM_);
        attn_mma_kernel<<<BS_ * H_, 256>>>();
        gemm_bf16_kernel<<<g768, 256>>>(SPL_ATT, OFF_WO + l * szAttL, bo + l * DM_,
                                        DM_, DM_, 0, 1, BUF_Q, 0);
        ln_residual_kernel<<<ROWS_, 256>>>(BUF_H, BUF_Q, l1g + l * DM_, l1b + l * DM_,
                                           BUF_H1, SPL_H1);
        gemm_bf16_kernel<<<g1024, 256>>>(SPL_H1, OFF_W1 + l * szFFL, b1 + l * FF_,
                                         FF_, DM_, 2, 2, 0, SPL_FF);
        gemm_bf16_kernel<<<g768, 256>>>(SPL_FF, OFF_W2 + l * szFFL, b2 + l * DM_,
                                        DM_, FF_, 0, 1, BUF_Q, 0);
        ln_residual_kernel<<<ROWS_, 256>>>(BUF_H1, BUF_Q, l2g + l * DM_, l2b + l * DM_,
                                           BUF_H, SPL_H);
    }

    gather_kernel<<<BS_ * A_, 256>>>(ats, lfg, lfb, out);
}

// round 12
// speedup vs baseline: 3.0722x; 1.0637x over previous
#include <cuda_runtime.h>
#include <cuda_bf16.h>
#include <math.h>
#include <stdint.h>

// Problem constants
#define T_      80
#define BS_     8
#define DM_     768
#define H_      4
#define DH_     192
#define FF_     1024
#define L_      4
#define LATENT_ 256
#define ROWS_   (T_ * BS_)      // 640
#define NJF_    150
#define A_      6

#define EPS_ATT 1e-6f
#define EPS_LN  1e-5f

typedef __nv_bfloat16 bf16;

// ---------------------------------------------------------------------------
// Scratch (device globals only; no cudaMalloc anywhere)
// ---------------------------------------------------------------------------
__device__ __align__(16) float g_h [ROWS_ * DM_];
__device__ __align__(16) float g_h1[ROWS_ * DM_];
__device__ __align__(16) float g_q [ROWS_ * DM_];   // fp32 GEMM temp

#define BUF_H   0
#define BUF_H1  1
#define BUF_Q   2

__device__ __forceinline__ float* scratch(int code)
{
    switch (code) {
        case BUF_H:  return g_h;
        case BUF_H1: return g_h1;
        default:     return g_q;
    }
}

// bf16 hi/lo split activations
__device__ __align__(16) bf16 s_h_hi  [ROWS_ * DM_];
__device__ __align__(16) bf16 s_h_lo  [ROWS_ * DM_];
__device__ __align__(16) bf16 s_att_hi[ROWS_ * DM_];
__device__ __align__(16) bf16 s_att_lo[ROWS_ * DM_];
__device__ __align__(16) bf16 s_h1_hi [ROWS_ * DM_];
__device__ __align__(16) bf16 s_h1_lo [ROWS_ * DM_];
__device__ __align__(16) bf16 s_ff_hi [ROWS_ * FF_];
__device__ __align__(16) bf16 s_ff_lo [ROWS_ * FF_];
__device__ __align__(16) bf16 s_q_hi  [ROWS_ * DM_];
__device__ __align__(16) bf16 s_q_lo  [ROWS_ * DM_];
__device__ __align__(16) bf16 s_k_hi  [ROWS_ * DM_];
__device__ __align__(16) bf16 s_k_lo  [ROWS_ * DM_];
__device__ __align__(16) bf16 s_v_hi  [ROWS_ * DM_];
__device__ __align__(16) bf16 s_v_lo  [ROWS_ * DM_];

#define SPL_H   0
#define SPL_ATT 1
#define SPL_H1  2
#define SPL_FF  3

__device__ __forceinline__ const bf16* split_hi(int c)
{
    switch (c) { case SPL_H: return s_h_hi; case SPL_ATT: return s_att_hi;
                 case SPL_H1: return s_h1_hi; default: return s_ff_hi; }
}
__device__ __forceinline__ const bf16* split_lo(int c)
{
    switch (c) { case SPL_H: return s_h_lo; case SPL_ATT: return s_att_lo;
                 case SPL_H1: return s_h1_lo; default: return s_ff_lo; }
}
__device__ __forceinline__ bf16* split_hi_w(int c)
{
    switch (c) { case SPL_H: return s_h_hi; case SPL_ATT: return s_att_hi;
                 case SPL_H1: return s_h1_hi; default: return s_ff_hi; }
}
__device__ __forceinline__ bf16* split_lo_w(int c)
{
    switch (c) { case SPL_H: return s_h_lo; case SPL_ATT: return s_att_lo;
                 case SPL_H1: return s_h1_lo; default: return s_ff_lo; }
}

__device__ __forceinline__ void split_store(float v, bf16* hi, bf16* lo, size_t idx)
{
    bf16 h = __float2bfloat16_rn(v);
    hi[idx] = h;
    lo[idx] = __float2bfloat16_rn(v - __bfloat162float(h));
}

// bf16 hi/lo split weights
#define SZW_ATT (L_ * DM_ * DM_)
#define SZW_FF  (L_ * DM_ * FF_)
#define OFF_WQ  ((size_t)0)
#define OFF_WK  ((size_t)SZW_ATT)
#define OFF_WV  ((size_t)(2 * SZW_ATT))
#define OFF_WO  ((size_t)(3 * SZW_ATT))
#define OFF_W1  ((size_t)(4 * SZW_ATT))
#define OFF_W2  ((size_t)(4 * SZW_ATT) + SZW_FF)
#define TOTALW  ((size_t)(4 * SZW_ATT) + 2 * (size_t)SZW_FF)

__device__ __align__(16) bf16 s_W_hi[TOTALW];
__device__ __align__(16) bf16 s_W_lo[TOTALW];

// ---------------------------------------------------------------------------
// Weight splitter
// ---------------------------------------------------------------------------
__global__ void split_weights_kernel(const float* __restrict__ Wq, const float* __restrict__ Wk,
                                     const float* __restrict__ Wv, const float* __restrict__ Wo,
                                     const float* __restrict__ W1, const float* __restrict__ W2)
{
    size_t i4 = ((size_t)blockIdx.x * blockDim.x + threadIdx.x) * 4;
    if (i4 >= TOTALW) return;

    const float* src;
    size_t rel;
    if (i4 < OFF_W1) {
        size_t seg = i4 / (size_t)SZW_ATT;
        rel = i4 - seg * (size_t)SZW_ATT;
        src = (seg == 0) ? Wq : (seg == 1) ? Wk : (seg == 2) ? Wv : Wo;
    } else if (i4 < OFF_W2) {
        src = W1; rel = i4 - OFF_W1;
    } else {
        src = W2; rel = i4 - OFF_W2;
    }

    float4 x = *(const float4*)(src + rel);
    const float xs[4] = {x.x, x.y, x.z, x.w};
    #pragma unroll
    for (int j = 0; j < 4; j++)
        split_store(xs[j], s_W_hi, s_W_lo, i4 + j);
}

// ---------------------------------------------------------------------------
// h0
// ---------------------------------------------------------------------------
__global__ void build_h0_kernel(const float* __restrict__ x,
                                const int*   __restrict__ y,
                                const int*   __restrict__ ind_map,
                                const float* __restrict__ skW,
                                const float* __restrict__ skb,
                                const float* __restrict__ muQ,
                                const float* __restrict__ sgQ)
{
    const int r = blockIdx.x;
    const int t = r / BS_;
    const int b = r - t * BS_;
    const int tid = threadIdx.x;

    __shared__ float xrow[NJF_];
    if (tid < NJF_) xrow[tid] = x[(size_t)b * NJF_ * T_ + tid * T_ + t];
    __syncthreads();

    const int a   = ind_map[t * BS_ + b];
    const int cls = y[b * A_ + a];
    const int start = (t == 0) ? 0 : (t + 2);

    const float div = expf(-(logf(10000.0f) / (float)LATENT_) * (float)(tid & ~1));
    const bool  odd = (tid & 1);

    float base0 = muQ[cls * LATENT_ + tid];
    float base1 = sgQ[cls * LATENT_ + tid];
    float acc = skb[tid];
    #pragma unroll 5
    for (int jf = 0; jf < NJF_; jf++) acc += xrow[jf] * skW[jf * LATENT_ + tid];

    const size_t base = (size_t)r * DM_;
    float v0, v1, v2;
    { float ang = (float)(start + 0) * div; v0 = base0 + (odd ? cosf(ang) : sinf(ang)); }
    { float ang = (float)(start + 1) * div; v1 = base1 + (odd ? cosf(ang) : sinf(ang)); }
    { float ang = (float)(start + 2) * div; v2 = acc   + (odd ? cosf(ang) : sinf(ang)); }

    g_h[base + tid]             = v0;
    g_h[base + tid + LATENT_]   = v1;
    g_h[base + tid + 2*LATENT_] = v2;
    split_store(v0, s_h_hi, s_h_lo, base + tid);
    split_store(v1, s_h_hi, s_h_lo, base + tid + LATENT_);
    split_store(v2, s_h_hi, s_h_lo, base + tid + 2*LATENT_);
}

// ---------------------------------------------------------------------------
// bf16 2-term split tensor-core GEMM (m16n8k16 + ldmatrix)
// ---------------------------------------------------------------------------
#define CTM 32
#define CTN 64
#define CTK 32
#define LDA_ 40
#define LDB_ 72

__device__ __forceinline__ uint32_t smem_u32(const void* p)
{
    return (uint32_t)__cvta_generic_to_shared(p);
}

__device__ __forceinline__ void ldm_x4(uint32_t* r, uint32_t addr)
{
    asm volatile("ldmatrix.sync.aligned.m8n8.x4.shared.b16 {%0,%1,%2,%3}, [%4];"
                 : "=r"(r[0]), "=r"(r[1]), "=r"(r[2]), "=r"(r[3]) : "r"(addr));
}
__device__ __forceinline__ void ldm_x4_t(uint32_t* r, uint32_t addr)
{
    asm volatile("ldmatrix.sync.aligned.m8n8.x4.trans.shared.b16 {%0,%1,%2,%3}, [%4];"
                 : "=r"(r[0]), "=r"(r[1]), "=r"(r[2]), "=r"(r[3]) : "r"(addr));
}
__device__ __forceinline__ void mma_bf16(float4& c, const uint32_t* a, uint32_t b0, uint32_t b1)
{
    asm volatile(
        "mma.sync.aligned.m16n8k16.row.col.f32.bf16.bf16.f32 "
        "{%0,%1,%2,%3},{%4,%5,%6,%7},{%8,%9},{%0,%1,%2,%3};"
        : "+f"(c.x), "+f"(c.y), "+f"(c.z), "+f"(c.w)
        : "r"(a[0]), "r"(a[1]), "r"(a[2]), "r"(a[3]), "r"(b0), "r"(b1));
}

__device__ __forceinline__ void gemm_bf16_core(
    const bf16* __restrict__ Ahi, const bf16* __restrict__ Alo,
    const bf16* __restrict__ Bhi, const bf16* __restrict__ Blo,
    const float* __restrict__ bias,
    float* Cf32, bf16* Shi, bf16* Slo,
    int N, int K, int rowBase, int colBase, int act, int outmode)
{
    __shared__ __align__(16) bf16 sA[2][2][CTM * LDA_];
    __shared__ __align__(16) bf16 sB[2][2][CTK * LDB_];
    __shared__ float red[2048];

    const int tid  = threadIdx.x;
    const int lane = tid & 31;
    const int wid  = tid >> 5;
    const int warp_m = wid & 1;
    const int warp_n = (wid >> 1) & 1;
    const int warp_k = wid >> 2;

    const int matA = tid >> 7;
    const int arem = tid & 127;
    const int ar = arem >> 2, ac = arem & 3;
    const int br = tid >> 3,  bc = tid & 7;

    const bf16* Asel = matA ? Alo : Ahi;
    const bf16* Agm  = Asel + (size_t)(rowBase + ar) * K + ac * 8;
    const bf16* Bgm_hi = Bhi + (size_t)br * N + colBase + bc * 8;
    const bf16* Bgm_lo = Blo + (size_t)br * N + colBase + bc * 8;

    bf16* AsmDst0 = &sA[0][matA][ar * LDA_ + ac * 8];
    bf16* AsmDst1 = &sA[1][matA][ar * LDA_ + ac * 8];
    bf16* BsmH0 = &sB[0][0][br * LDB_ + bc * 8];
    bf16* BsmH1 = &sB[1][0][br * LDB_ + bc * 8];
    bf16* BsmL0 = &sB[0][1][br * LDB_ + bc * 8];
    bf16* BsmL1 = &sB[1][1][br * LDB_ + bc * 8];

    const int aoff  = (warp_m * 16 + (lane & 15)) * LDA_ + warp_k * 16 + (lane >> 4) * 8;
    const int boff0 = (warp_k * 16 + (lane & 15)) * LDB_ + warp_n * 32 + (lane >> 4) * 8;
    const int boff1 = boff0 + 16;

    float4 acc[4] = {{0,0,0,0},{0,0,0,0},{0,0,0,0},{0,0,0,0}};

    const int KT = K / CTK;

    {
        uint4 pa = *(const uint4*)Agm;
        uint4 pb0 = *(const uint4*)Bgm_hi;
        uint4 pb1 = *(const uint4*)Bgm_lo;
        *(uint4*)AsmDst0 = pa;
        *(uint4*)BsmH0 = pb0;
        *(uint4*)BsmL0 = pb1;
    }
    __syncthreads();

    int buf = 0;
    for (int kt = 0; kt < KT; kt++) {
        uint4 pa, pb0, pb1;
        const bool more = (kt + 1 < KT);
        if (more) {
            pa  = *(const uint4*)(Agm + (kt + 1) * CTK);
            pb0 = *(const uint4*)(Bgm_hi + (size_t)(kt + 1) * CTK * N);
            pb1 = *(const uint4*)(Bgm_lo + (size_t)(kt + 1) * CTK * N);
        }

        uint32_t ah[4], al[4], bh0[4], bh1[4], bl0[4], bl1[4];
        ldm_x4  (ah,  smem_u32(&sA[buf][0][aoff]));
        ldm_x4  (al,  smem_u32(&sA[buf][1][aoff]));
        ldm_x4_t(bh0, smem_u32(&sB[buf][0][boff0]));
        ldm_x4_t(bh1, smem_u32(&sB[buf][0][boff1]));
        ldm_x4_t(bl0, smem_u32(&sB[buf][1][boff0]));
        ldm_x4_t(bl1, smem_u32(&sB[buf][1][boff1]));

        mma_bf16(acc[0], ah, bh0[0], bh0[1]);
        mma_bf16(acc[0], ah, bl0[0], bl0[1]);
        mma_bf16(acc[0], al, bh0[0], bh0[1]);

        mma_bf16(acc[1], ah, bh0[2], bh0[3]);
        mma_bf16(acc[1], ah, bl0[2], bl0[3]);
        mma_bf16(acc[1], al, bh0[2], bh0[3]);

        mma_bf16(acc[2], ah, bh1[0], bh1[1]);
        mma_bf16(acc[2], ah, bl1[0], bl1[1]);
        mma_bf16(acc[2], al, bh1[0], bh1[1]);

        mma_bf16(acc[3], ah, bh1[2], bh1[3]);
        mma_bf16(acc[3], ah, bl1[2], bl1[3]);
        mma_bf16(acc[3], al, bh1[2], bh1[3]);

        if (more) {
            if (buf == 0) { *(uint4*)AsmDst1 = pa; *(uint4*)BsmH1 = pb0; *(uint4*)BsmL1 = pb1; }
            else          { *(uint4*)AsmDst0 = pa; *(uint4*)BsmH0 = pb0; *(uint4*)BsmL0 = pb1; }
        }
        __syncthreads();
        buf ^= 1;
    }

    float* af = reinterpret_cast<float*>(acc);
    if (warp_k == 1) {
        int base = (wid - 4) * 32 + lane;
        #pragma unroll
        for (int j = 0; j < 16; j++) red[j * 128 + base] = af[j];
    }
    __syncthreads();
    if (warp_k == 0) {
        int base = wid * 32 + lane;
        #pragma unroll
        for (int j = 0; j < 16; j++) af[j] += red[j * 128 + base];

        const int row0 = rowBase + warp_m * 16 + (lane >> 2);
        #pragma unroll
        for (int nt = 0; nt < 4; nt++) {
            const int col = colBase + warp_n * 32 + nt * 8 + 2 * (lane & 3);
            float2 bb = *(const float2*)(bias + col);
            float v00 = acc[nt].x + bb.x, v01 = acc[nt].y + bb.y;
            float v10 = acc[nt].z + bb.x, v11 = acc[nt].w + bb.y;
            if (act == 1) {
                v00 = (v00 > 0.f) ? (v00 + 1.f) : expf(v00);
                v01 = (v01 > 0.f) ? (v01 + 1.f) : expf(v01);
                v10 = (v10 > 0.f) ? (v10 + 1.f) : expf(v10);
                v11 = (v11 > 0.f) ? (v11 + 1.f) : expf(v11);
            } else if (act == 2) {
                v00 = fmaxf(v00, 0.f); v01 = fmaxf(v01, 0.f);
                v10 = fmaxf(v10, 0.f); v11 = fmaxf(v11, 0.f);
            }
            if (outmode & 1) {
                *(float2*)(Cf32 + (size_t)row0 * N + col)       = make_float2(v00, v01);
                *(float2*)(Cf32 + (size_t)(row0 + 8) * N + col) = make_float2(v10, v11);
            }
            if (outmode & 2) {
                split_store(v00, Shi, Slo, (size_t)row0 * N + col);
                split_store(v01, Shi, Slo, (size_t)row0 * N + col + 1);
                split_store(v10, Shi, Slo, (size_t)(row0 + 8) * N + col);
                split_store(v11, Shi, Slo, (size_t)(row0 + 8) * N + col + 1);
            }
        }
    }
}

__global__ void gemm_bf16_kernel(int a_code, size_t w_off, const float* __restrict__ bias,
                                 int N, int K, int act, int outmode, int c_code, int s_code)
{
    float* Cf32 = (outmode & 1) ? scratch(c_code) : nullptr;
    bf16* Shi = (outmode & 2) ? split_hi_w(s_code) : nullptr;
    bf16* Slo = (outmode & 2) ? split_lo_w(s_code) : nullptr;
    gemm_bf16_core(split_hi(a_code), split_lo(a_code),
                   s_W_hi + w_off, s_W_lo + w_off, bias,
                   Cf32, Shi, Slo, N, K,
                   blockIdx.y * CTM, blockIdx.x * CTN, act, outmode);
}

__global__ void gemm_qkv_bf16_kernel(size_t offq, size_t offk, size_t offv,
                                     const float* __restrict__ bq,
                                     const float* __restrict__ bk,
                                     const float* __restrict__ bv)
{
    const int gcol = blockIdx.x * CTN;
    const int mat  = gcol / DM_;
    const int colBase = gcol - mat * DM_;
    size_t w_off      = (mat == 0) ? offq : (mat == 1) ? offk : offv;
    const float* bias = (mat == 0) ? bq   : (mat == 1) ? bk   : bv;
    bf16* shi         = (mat == 0) ? s_q_hi : (mat == 1) ? s_k_hi : s_v_hi;
    bf16* slo         = (mat == 0) ? s_q_lo : (mat == 1) ? s_k_lo : s_v_lo;
    const int act     = (mat < 2) ? 1 : 0;
    gemm_bf16_core(s_h_hi, s_h_lo, s_W_hi + w_off, s_W_lo + w_off, bias,
                   nullptr, shi, slo, DM_, DM_,
                   blockIdx.y * CTM, colBase, act, 2);
}

// ---------------------------------------------------------------------------
// Tensor-core causal linear attention, query-chunked.
// Grid (5 mchunks, 32 bh), 256 threads / 8 warps.
// Block (mc,bh): rows [16mc, 16mc+16). W = (mc+1)*16 key columns.
// Phase A: warp w (w<=mc) owns tau-chunk w; K streamed per 16-d chunk.
// Phase C: warps own d16 tiles (w and w+8); V streamed per 16-tau chunk.
// ---------------------------------------------------------------------------
#define QLD 24      // 16 + 8 pad
#define SLD 88      // 80 + 8 pad
#define VLD 200     // 192 + 8 pad

__device__ __forceinline__ void split2smem(float v, bf16* hi, bf16* lo, int idx)
{
    bf16 h = __float2bfloat16_rn(v);
    hi[idx] = h;
    lo[idx] = __float2bfloat16_rn(v - __bfloat162float(h));
}

__global__ void attn_mma_kernel()
{
    __shared__ __align__(16) bf16 sSh[16 * SLD];     // 2816 B
    __shared__ __align__(16) bf16 sSl[16 * SLD];
    __shared__ __align__(16) bf16 stage[6400];       // 12.8 KB, reused A/C
    __shared__ float inv_s[16];

    const int mc = blockIdx.x;           // 0..4
    const int bh = blockIdx.y;           // 0..31
    const int b = bh >> 2, h = bh & 3;
    const int t0 = mc * 16;
    const int W  = (mc + 1) * 16;
    const int tid = threadIdx.x, lane = tid & 31, wid = tid >> 5;
    const int g = lane >> 2, tq = lane & 3;

    // ---------------- Phase A: S = Q K^T ----------------
    // stage: Qh[0,384) Ql[384,768) Kh[768,768+1920) Kl[2688, 2688+1920)
    float4 accA[2] = {{0,0,0,0},{0,0,0,0}};

    const int kld_per_plane = W * 2;                 // uint4 loads per K plane
    const int totA = 64 + 2 * kld_per_plane;         // <= 384

    for (int kc = 0; kc < 12; kc++) {
        __syncthreads();
        for (int i = tid; i < totA; i += 256) {
            if (i < 64) {
                int p = i >> 5, rem = i & 31;
                int row = rem >> 1, cg = (rem & 1) << 3;
                const bf16* src = p ? s_q_lo : s_q_hi;
                *(uint4*)&stage[p * 384 + row * QLD + cg] =
                    *(const uint4*)&src[(size_t)((t0 + row) * BS_ + b) * DM_ + h * DH_ + kc * 16 + cg];
            } else {
                int j = i - 64;
                int p = j / kld_per_plane, rem = j - p * kld_per_plane;
                int row = rem >> 1, cg = (rem & 1) << 3;
                const bf16* src = p ? s_k_lo : s_k_hi;
                *(uint4*)&stage[768 + p * 1920 + row * QLD + cg] =
                    *(const uint4*)&src[(size_t)(row * BS_ + b) * DM_ + h * DH_ + kc * 16 + cg];
            }
        }
        __syncthreads();

        if (wid <= mc) {
            uint32_t qh[4], ql[4], kh[4], kl[4];
            int aoff = (lane & 15) * QLD + ((lane >> 4) << 3);
            int koff = (wid * 16 + (lane & 15)) * QLD + ((lane >> 4) << 3);
            ldm_x4(qh, smem_u32(&stage[aoff]));
            ldm_x4(ql, smem_u32(&stage[384 + aoff]));
            ldm_x4(kh, smem_u32(&stage[768 + koff]));
            ldm_x4(kl, smem_u32(&stage[2688 + koff]));
            mma_bf16(accA[0], qh, kh[0], kh[2]);
            mma_bf16(accA[0], qh, kl[0], kl[2]);
            mma_bf16(accA[0], ql, kh[0], kh[2]);
            mma_bf16(accA[1], qh, kh[1], kh[3]);
            mma_bf16(accA[1], qh, kl[1], kl[3]);
            mma_bf16(accA[1], ql, kh[1], kh[3]);
        }
    }
    __syncthreads();

    // masked split store of S chunk (warp w -> cols [16w,16w+16))
    if (wid <= mc) {
        int r0 = g, r1 = g + 8;           // local rows
        #pragma unroll
        for (int n8 = 0; n8 < 2; n8++) {
            int c = wid * 16 + n8 * 8 + 2 * tq;     // global col
            float4 a = accA[n8];
            split2smem((c     <= t0 + r0) ? a.x : 0.f, sSh, sSl, r0 * SLD + c);
            split2smem((c + 1 <= t0 + r0) ? a.y : 0.f, sSh, sSl, r0 * SLD + c + 1);
            split2smem((c     <= t0 + r1) ? a.z : 0.f, sSh, sSl, r1 * SLD + c);
            split2smem((c + 1 <= t0 + r1) ? a.w : 0.f, sSh, sSl, r1 * SLD + c + 1);
        }
    }
    __syncthreads();

    if (tid < 16) {
        float s = 0.0f;
        for (int c = 0; c < W; c++)
            s += __bfloat162float(sSh[tid * SLD + c]) + __bfloat162float(sSl[tid * SLD + c]);
        inv_s[tid] = 1.0f / (s + EPS_ATT);
    }

    // ---------------- Phase C: O = S V ----------------
    // stage: Vh[0,3200) Vl[3200,6400)
    float4 accC[2][2];
    #pragma unroll
    for (int j = 0; j < 2; j++) { accC[j][0] = make_float4(0,0,0,0); accC[j][1] = make_float4(0,0,0,0); }

    for (int vc = 0; vc <= mc; vc++) {
        __syncthreads();
        for (int i = tid; i < 768; i += 256) {
            int p = i / 384, rem = i - p * 384;
            int row = rem / 24, cg = (rem - row * 24) << 3;
            const bf16* src = p ? s_v_lo : s_v_hi;
            *(uint4*)&stage[p * 3200 + row * VLD + cg] =
                *(const uint4*)&src[(size_t)((vc * 16 + row) * BS_ + b) * DM_ + h * DH_ + cg];
        }
        __syncthreads();

        uint32_t sh[4], sl[4];
        int aoff = (lane & 15) * SLD + vc * 16 + ((lane >> 4) << 3);
        ldm_x4(sh, smem_u32(&sSh[aoff]));
        ldm_x4(sl, smem_u32(&sSl[aoff]));

        #pragma unroll
        for (int j = 0; j < 2; j++) {
            int ni = wid + 8 * j;
            if (ni < 12) {
                uint32_t vh[4], vl[4];
                int boff = (lane & 15) * VLD + ni * 16 + ((lane >> 4) << 3);
                ldm_x4_t(vh, smem_u32(&stage[boff]));
                ldm_x4_t(vl, smem_u32(&stage[3200 + boff]));
                mma_bf16(accC[j][0], sh, vh[0], vh[1]);
                mma_bf16(accC[j][0], sh, vl[0], vl[1]);
                mma_bf16(accC[j][0], sl, vh[0], vh[1]);
                mma_bf16(accC[j][1], sh, vh[2], vh[3]);
                mma_bf16(accC[j][1], sh, vl[2], vl[3]);
                mma_bf16(accC[j][1], sl, vh[2], vh[3]);
            }
        }
    }

    // output: scale by inv, split-store to s_att
    {
        int r0 = g, r1 = g + 8;
        float i0 = inv_s[r0], i1 = inv_s[r1];
        #pragma unroll
        for (int j = 0; j < 2; j++) {
            int ni = wid + 8 * j;
            if (ni < 12) {
                #pragma unroll
                for (int n8 = 0; n8 < 2; n8++) {
                    int d = ni * 16 + n8 * 8 + 2 * tq;
                    float4 a = accC[j][n8];
                    size_t o0 = (size_t)((t0 + r0) * BS_ + b) * DM_ + h * DH_ + d;
                    size_t o1 = (size_t)((t0 + r1) * BS_ + b) * DM_ + h * DH_ + d;
                    split_store(a.x * i0, s_att_hi, s_att_lo, o0);
                    split_store(a.y * i0, s_att_hi, s_att_lo, o0 + 1);
                    split_store(a.z * i1, s_att_hi, s_att_lo, o1);
                    split_store(a.w * i1, s_att_hi, s_att_lo, o1 + 1);
                }
            }
        }
    }
}

// ---------------------------------------------------------------------------
// LayerNorm helpers
// ---------------------------------------------------------------------------
__device__ __forceinline__ float block_sum_256(float val)
{
    __shared__ float sh[8];
    const int lane = threadIdx.x & 31;
    const int w    = threadIdx.x >> 5;
    #pragma unroll
    for (int o = 16; o > 0; o >>= 1) val += __shfl_down_sync(0xffffffffu, val, o);
    if (lane == 0) sh[w] = val;
    __syncthreads();
    if (w == 0) {
        float r = (lane < 8) ? sh[lane] : 0.0f;
        #pragma unroll
        for (int o = 4; o > 0; o >>= 1) r += __shfl_down_sync(0xffffffffu, r, o);
        if (lane == 0) sh[0] = r;
    }
    __syncthreads();
    float res = sh[0];
    __syncthreads();
    return res;
}

__global__ void ln_residual_kernel(int x_code, int y_code,
                                   const float* __restrict__ g, const float* __restrict__ bt,
                                   int out_code, int s_code)
{
    const float* x  = scratch(x_code);
    const float* yv = scratch(y_code);
    float* out      = scratch(out_code);
    bf16* shi = split_hi_w(s_code);
    bf16* slo = split_lo_w(s_code);

    const int row = blockIdx.x;
    const int tid = threadIdx.x;
    const size_t base = (size_t)row * DM_;

    float v0 = x[base + tid]       + yv[base + tid];
    float v1 = x[base + tid + 256] + yv[base + tid + 256];
    float v2 = x[base + tid + 512] + yv[base + tid + 512];

    float mean = block_sum_256(v0 + v1 + v2) * (1.0f / (float)DM_);
    float d0 = v0 - mean, d1 = v1 - mean, d2 = v2 - mean;
    float var = block_sum_256(d0*d0 + d1*d1 + d2*d2) * (1.0f / (float)DM_);
    float rstd = rsqrtf(var + EPS_LN);

    float o0 = d0 * rstd * g[tid]       + bt[tid];
    float o1 = d1 * rstd * g[tid + 256] + bt[tid + 256];
    float o2 = d2 * rstd * g[tid + 512] + bt[tid + 512];

    out[base + tid]       = o0;
    out[base + tid + 256] = o1;
    out[base + tid + 512] = o2;
    split_store(o0, shi, slo, base + tid);
    split_store(o1, shi, slo, base + tid + 256);
    split_store(o2, shi, slo, base + tid + 512);
}

// ---------------------------------------------------------------------------
// Final gather + LN
// ---------------------------------------------------------------------------
__global__ void gather_kernel(const int* __restrict__ act_ts,
                              const float* __restrict__ g, const float* __restrict__ bt,
                              float* __restrict__ out)
{
    const int ba = blockIdx.x;
    const int b  = ba / A_;
    int t = act_ts[ba] - 1;
    if (t < 0) t = 0;
    const int row = t * BS_ + b;
    const int tid = threadIdx.x;
    const size_t base = (size_t)row * DM_;

    float v0 = g_h[base + tid];
    float v1 = g_h[base + tid + 256];
    float v2 = g_h[base + tid + 512];

    float mean = block_sum_256(v0 + v1 + v2) * (1.0f / (float)DM_);
    float d0 = v0 - mean, d1 = v1 - mean, d2 = v2 - mean;
    float var = block_sum_256(d0*d0 + d1*d1 + d2*d2) * (1.0f / (float)DM_);
    float rstd = rsqrtf(var + EPS_LN);

    out[(size_t)ba * LATENT_ + tid]                      = d0 * rstd * g[tid]       + bt[tid];
    out[(size_t)BS_ * A_ * LATENT_ + ba * LATENT_ + tid] = d1 * rstd * g[tid + 256] + bt[tid + 256];
}

// ---------------------------------------------------------------------------
// Host orchestration: kernel launches ONLY
// ---------------------------------------------------------------------------
extern "C" void kernel_launch(void* const* d_in, const int* in_sizes, int n_in,
                              void* d_out, int out_size)
{
    const float* x    = (const float*)d_in[0];
    const int*   y    = (const int*)  d_in[1];
    const int*   ind  = (const int*)  d_in[2];
    const int*   ats  = (const int*)  d_in[3];
    const float* skW  = (const float*)d_in[4];
    const float* skb  = (const float*)d_in[5];
    const float* muQ  = (const float*)d_in[6];
    const float* sgQ  = (const float*)d_in[7];
    const float* Wq   = (const float*)d_in[8];
    const float* bq   = (const float*)d_in[9];
    const float* Wk   = (const float*)d_in[10];
    const float* bk   = (const float*)d_in[11];
    const float* Wv   = (const float*)d_in[12];
    const float* bv   = (const float*)d_in[13];
    const float* Wo   = (const float*)d_in[14];
    const float* bo   = (const float*)d_in[15];
    const float* W1   = (const float*)d_in[16];
    const float* b1   = (const float*)d_in[17];
    const float* W2   = (const float*)d_in[18];
    const float* b2   = (const float*)d_in[19];
    const float* l1g  = (const float*)d_in[20];
    const float* l1b  = (const float*)d_in[21];
    const float* l2g  = (const float*)d_in[22];
    const float* l2b  = (const float*)d_in[23];
    const float* lfg  = (const float*)d_in[24];
    const float* lfb  = (const float*)d_in[25];
    float* out = (float*)d_out;

    split_weights_kernel<<<(unsigned)((TOTALW / 4 + 255) / 256), 256>>>(Wq, Wk, Wv, Wo, W1, W2);
    build_h0_kernel<<<ROWS_, 256>>>(x, y, ind, skW, skb, muQ, sgQ);

    const dim3 gQKV(3 * DM_ / CTN, ROWS_ / CTM);   // 36 x 20
    const dim3 g768(DM_ / CTN, ROWS_ / CTM);       // 12 x 20
    const dim3 g1024(FF_ / CTN, ROWS_ / CTM);      // 16 x 20
    const dim3 gAttn(5, BS_ * H_);                 // 5 mchunks x 32 bh = 160

    const size_t szAttL = (size_t)DM_ * DM_;
    const size_t szFFL  = (size_t)DM_ * FF_;

    for (int l = 0; l < L_; l++) {
        gemm_qkv_bf16_kernel<<<gQKV, 256>>>(OFF_WQ + l * szAttL,
                                            OFF_WK + l * szAttL,
                                            OFF_WV + l * szAttL,
                                            bq + l * DM_, bk + l * DM_, bv + l * DM_);
        attn_mma_kernel<<<gAttn, 256>>>();
        gemm_bf16_kernel<<<g768, 256>>>(SPL_ATT, OFF_WO + l * szAttL, bo + l * DM_,
                                        DM_, DM_, 0, 1, BUF_Q, 0);
        ln_residual_kernel<<<ROWS_, 256>>>(BUF_H, BUF_Q, l1g + l * DM_, l1b + l * DM_,
                                           BUF_H1, SPL_H1);
        gemm_bf16_kernel<<<g1024, 256>>>(SPL_H1, OFF_W1 + l * szFFL, b1 + l * FF_,
                                         FF_, DM_, 2, 2, 0, SPL_FF);
        gemm_bf16_kernel<<<g768, 256>>>(SPL_FF, OFF_W2 + l * szFFL, b2 + l * DM_,
                                        DM_, FF_, 0, 1, BUF_Q, 0);
        ln_residual_kernel<<<ROWS_, 256>>>(BUF_H1, BUF_Q, l2g + l * DM_, l2b + l * DM_,
                                           BUF_H, SPL_H);
    }

    gather_kernel<<<BS_ * A_, 256>>>(ats, lfg, lfb, out);
}

// round 13
// speedup vs baseline: 3.1358x; 1.0207x over previous
#include <cuda_runtime.h>
#include <cuda_bf16.h>
#include <math.h>
#include <stdint.h>

// Problem constants
#define T_      80
#define BS_     8
#define DM_     768
#define H_      4
#define DH_     192
#define FF_     1024
#define L_      4
#define LATENT_ 256
#define ROWS_   (T_ * BS_)      // 640
#define NJF_    150
#define A_      6

#define EPS_ATT 1e-6f
#define EPS_LN  1e-5f

typedef __nv_bfloat16 bf16;

// ---------------------------------------------------------------------------
// Scratch (device globals only; no cudaMalloc anywhere)
// ---------------------------------------------------------------------------
__device__ __align__(16) float g_h [ROWS_ * DM_];
__device__ __align__(16) float g_h1[ROWS_ * DM_];
__device__ __align__(16) float g_q [ROWS_ * DM_];   // fp32 GEMM temp

#define BUF_H   0
#define BUF_H1  1
#define BUF_Q   2

__device__ __forceinline__ float* scratch(int code)
{
    switch (code) {
        case BUF_H:  return g_h;
        case BUF_H1: return g_h1;
        default:     return g_q;
    }
}

// bf16 hi/lo split activations
__device__ __align__(16) bf16 s_h_hi  [ROWS_ * DM_];
__device__ __align__(16) bf16 s_h_lo  [ROWS_ * DM_];
__device__ __align__(16) bf16 s_att_hi[ROWS_ * DM_];
__device__ __align__(16) bf16 s_att_lo[ROWS_ * DM_];
__device__ __align__(16) bf16 s_h1_hi [ROWS_ * DM_];
__device__ __align__(16) bf16 s_h1_lo [ROWS_ * DM_];
__device__ __align__(16) bf16 s_ff_hi [ROWS_ * FF_];
__device__ __align__(16) bf16 s_ff_lo [ROWS_ * FF_];
__device__ __align__(16) bf16 s_q_hi  [ROWS_ * DM_];
__device__ __align__(16) bf16 s_q_lo  [ROWS_ * DM_];
__device__ __align__(16) bf16 s_k_hi  [ROWS_ * DM_];
__device__ __align__(16) bf16 s_k_lo  [ROWS_ * DM_];
__device__ __align__(16) bf16 s_v_hi  [ROWS_ * DM_];
__device__ __align__(16) bf16 s_v_lo  [ROWS_ * DM_];

#define SPL_H   0
#define SPL_ATT 1
#define SPL_H1  2
#define SPL_FF  3

__device__ __forceinline__ const bf16* split_hi(int c)
{
    switch (c) { case SPL_H: return s_h_hi; case SPL_ATT: return s_att_hi;
                 case SPL_H1: return s_h1_hi; default: return s_ff_hi; }
}
__device__ __forceinline__ const bf16* split_lo(int c)
{
    switch (c) { case SPL_H: return s_h_lo; case SPL_ATT: return s_att_lo;
                 case SPL_H1: return s_h1_lo; default: return s_ff_lo; }
}
__device__ __forceinline__ bf16* split_hi_w(int c)
{
    switch (c) { case SPL_H: return s_h_hi; case SPL_ATT: return s_att_hi;
                 case SPL_H1: return s_h1_hi; default: return s_ff_hi; }
}
__device__ __forceinline__ bf16* split_lo_w(int c)
{
    switch (c) { case SPL_H: return s_h_lo; case SPL_ATT: return s_att_lo;
                 case SPL_H1: return s_h1_lo; default: return s_ff_lo; }
}

__device__ __forceinline__ void split_store(float v, bf16* hi, bf16* lo, size_t idx)
{
    bf16 h = __float2bfloat16_rn(v);
    hi[idx] = h;
    lo[idx] = __float2bfloat16_rn(v - __bfloat162float(h));
}

// bf16 hi/lo split weights
#define SZW_ATT (L_ * DM_ * DM_)
#define SZW_FF  (L_ * DM_ * FF_)
#define OFF_WQ  ((size_t)0)
#define OFF_WK  ((size_t)SZW_ATT)
#define OFF_WV  ((size_t)(2 * SZW_ATT))
#define OFF_WO  ((size_t)(3 * SZW_ATT))
#define OFF_W1  ((size_t)(4 * SZW_ATT))
#define OFF_W2  ((size_t)(4 * SZW_ATT) + SZW_FF)
#define TOTALW  ((size_t)(4 * SZW_ATT) + 2 * (size_t)SZW_FF)

__device__ __align__(16) bf16 s_W_hi[TOTALW];
__device__ __align__(16) bf16 s_W_lo[TOTALW];

// ---------------------------------------------------------------------------
// Weight splitter
// ---------------------------------------------------------------------------
__global__ void split_weights_kernel(const float* __restrict__ Wq, const float* __restrict__ Wk,
                                     const float* __restrict__ Wv, const float* __restrict__ Wo,
                                     const float* __restrict__ W1, const float* __restrict__ W2)
{
    size_t i4 = ((size_t)blockIdx.x * blockDim.x + threadIdx.x) * 4;
    if (i4 >= TOTALW) return;

    const float* src;
    size_t rel;
    if (i4 < OFF_W1) {
        size_t seg = i4 / (size_t)SZW_ATT;
        rel = i4 - seg * (size_t)SZW_ATT;
        src = (seg == 0) ? Wq : (seg == 1) ? Wk : (seg == 2) ? Wv : Wo;
    } else if (i4 < OFF_W2) {
        src = W1; rel = i4 - OFF_W1;
    } else {
        src = W2; rel = i4 - OFF_W2;
    }

    float4 x = *(const float4*)(src + rel);
    const float xs[4] = {x.x, x.y, x.z, x.w};
    #pragma unroll
    for (int j = 0; j < 4; j++)
        split_store(xs[j], s_W_hi, s_W_lo, i4 + j);
}

// ---------------------------------------------------------------------------
// h0
// ---------------------------------------------------------------------------
__global__ void build_h0_kernel(const float* __restrict__ x,
                                const int*   __restrict__ y,
                                const int*   __restrict__ ind_map,
                                const float* __restrict__ skW,
                                const float* __restrict__ skb,
                                const float* __restrict__ muQ,
                                const float* __restrict__ sgQ)
{
    const int r = blockIdx.x;
    const int t = r / BS_;
    const int b = r - t * BS_;
    const int tid = threadIdx.x;

    __shared__ float xrow[NJF_];
    if (tid < NJF_) xrow[tid] = x[(size_t)b * NJF_ * T_ + tid * T_ + t];
    __syncthreads();

    const int a   = ind_map[t * BS_ + b];
    const int cls = y[b * A_ + a];
    const int start = (t == 0) ? 0 : (t + 2);

    const float div = expf(-(logf(10000.0f) / (float)LATENT_) * (float)(tid & ~1));
    const bool  odd = (tid & 1);

    float base0 = muQ[cls * LATENT_ + tid];
    float base1 = sgQ[cls * LATENT_ + tid];
    float acc = skb[tid];
    #pragma unroll 5
    for (int jf = 0; jf < NJF_; jf++) acc += xrow[jf] * skW[jf * LATENT_ + tid];

    const size_t base = (size_t)r * DM_;
    float v0, v1, v2;
    { float ang = (float)(start + 0) * div; v0 = base0 + (odd ? cosf(ang) : sinf(ang)); }
    { float ang = (float)(start + 1) * div; v1 = base1 + (odd ? cosf(ang) : sinf(ang)); }
    { float ang = (float)(start + 2) * div; v2 = acc   + (odd ? cosf(ang) : sinf(ang)); }

    g_h[base + tid]             = v0;
    g_h[base + tid + LATENT_]   = v1;
    g_h[base + tid + 2*LATENT_] = v2;
    split_store(v0, s_h_hi, s_h_lo, base + tid);
    split_store(v1, s_h_hi, s_h_lo, base + tid + LATENT_);
    split_store(v2, s_h_hi, s_h_lo, base + tid + 2*LATENT_);
}

// ---------------------------------------------------------------------------
// bf16 2-term split tensor-core GEMM (m16n8k16 + ldmatrix)
// ---------------------------------------------------------------------------
#define CTM 32
#define CTN 64
#define CTK 32
#define LDA_ 40
#define LDB_ 72

__device__ __forceinline__ uint32_t smem_u32(const void* p)
{
    return (uint32_t)__cvta_generic_to_shared(p);
}

__device__ __forceinline__ void ldm_x4(uint32_t* r, uint32_t addr)
{
    asm volatile("ldmatrix.sync.aligned.m8n8.x4.shared.b16 {%0,%1,%2,%3}, [%4];"
                 : "=r"(r[0]), "=r"(r[1]), "=r"(r[2]), "=r"(r[3]) : "r"(addr));
}
__device__ __forceinline__ void ldm_x4_t(uint32_t* r, uint32_t addr)
{
    asm volatile("ldmatrix.sync.aligned.m8n8.x4.trans.shared.b16 {%0,%1,%2,%3}, [%4];"
                 : "=r"(r[0]), "=r"(r[1]), "=r"(r[2]), "=r"(r[3]) : "r"(addr));
}
__device__ __forceinline__ void mma_bf16(float4& c, const uint32_t* a, uint32_t b0, uint32_t b1)
{
    asm volatile(
        "mma.sync.aligned.m16n8k16.row.col.f32.bf16.bf16.f32 "
        "{%0,%1,%2,%3},{%4,%5,%6,%7},{%8,%9},{%0,%1,%2,%3};"
        : "+f"(c.x), "+f"(c.y), "+f"(c.z), "+f"(c.w)
        : "r"(a[0]), "r"(a[1]), "r"(a[2]), "r"(a[3]), "r"(b0), "r"(b1));
}

__device__ __forceinline__ void gemm_bf16_core(
    const bf16* __restrict__ Ahi, const bf16* __restrict__ Alo,
    const bf16* __restrict__ Bhi, const bf16* __restrict__ Blo,
    const float* __restrict__ bias,
    float* Cf32, bf16* Shi, bf16* Slo,
    int N, int K, int rowBase, int colBase, int act, int outmode)
{
    __shared__ __align__(16) bf16 sA[2][2][CTM * LDA_];
    __shared__ __align__(16) bf16 sB[2][2][CTK * LDB_];
    __shared__ float red[2048];

    const int tid  = threadIdx.x;
    const int lane = tid & 31;
    const int wid  = tid >> 5;
    const int warp_m = wid & 1;
    const int warp_n = (wid >> 1) & 1;
    const int warp_k = wid >> 2;

    const int matA = tid >> 7;
    const int arem = tid & 127;
    const int ar = arem >> 2, ac = arem & 3;
    const int br = tid >> 3,  bc = tid & 7;

    const bf16* Asel = matA ? Alo : Ahi;
    const bf16* Agm  = Asel + (size_t)(rowBase + ar) * K + ac * 8;
    const bf16* Bgm_hi = Bhi + (size_t)br * N + colBase + bc * 8;
    const bf16* Bgm_lo = Blo + (size_t)br * N + colBase + bc * 8;

    bf16* AsmDst0 = &sA[0][matA][ar * LDA_ + ac * 8];
    bf16* AsmDst1 = &sA[1][matA][ar * LDA_ + ac * 8];
    bf16* BsmH0 = &sB[0][0][br * LDB_ + bc * 8];
    bf16* BsmH1 = &sB[1][0][br * LDB_ + bc * 8];
    bf16* BsmL0 = &sB[0][1][br * LDB_ + bc * 8];
    bf16* BsmL1 = &sB[1][1][br * LDB_ + bc * 8];

    const int aoff  = (warp_m * 16 + (lane & 15)) * LDA_ + warp_k * 16 + (lane >> 4) * 8;
    const int boff0 = (warp_k * 16 + (lane & 15)) * LDB_ + warp_n * 32 + (lane >> 4) * 8;
    const int boff1 = boff0 + 16;

    float4 acc[4] = {{0,0,0,0},{0,0,0,0},{0,0,0,0},{0,0,0,0}};

    const int KT = K / CTK;

    {
        uint4 pa = *(const uint4*)Agm;
        uint4 pb0 = *(const uint4*)Bgm_hi;
        uint4 pb1 = *(const uint4*)Bgm_lo;
        *(uint4*)AsmDst0 = pa;
        *(uint4*)BsmH0 = pb0;
        *(uint4*)BsmL0 = pb1;
    }
    __syncthreads();

    int buf = 0;
    for (int kt = 0; kt < KT; kt++) {
        uint4 pa, pb0, pb1;
        const bool more = (kt + 1 < KT);
        if (more) {
            pa  = *(const uint4*)(Agm + (kt + 1) * CTK);
            pb0 = *(const uint4*)(Bgm_hi + (size_t)(kt + 1) * CTK * N);
            pb1 = *(const uint4*)(Bgm_lo + (size_t)(kt + 1) * CTK * N);
        }

        uint32_t ah[4], al[4], bh0[4], bh1[4], bl0[4], bl1[4];
        ldm_x4  (ah,  smem_u32(&sA[buf][0][aoff]));
        ldm_x4  (al,  smem_u32(&sA[buf][1][aoff]));
        ldm_x4_t(bh0, smem_u32(&sB[buf][0][boff0]));
        ldm_x4_t(bh1, smem_u32(&sB[buf][0][boff1]));
        ldm_x4_t(bl0, smem_u32(&sB[buf][1][boff0]));
        ldm_x4_t(bl1, smem_u32(&sB[buf][1][boff1]));

        mma_bf16(acc[0], ah, bh0[0], bh0[1]);
        mma_bf16(acc[0], ah, bl0[0], bl0[1]);
        mma_bf16(acc[0], al, bh0[0], bh0[1]);

        mma_bf16(acc[1], ah, bh0[2], bh0[3]);
        mma_bf16(acc[1], ah, bl0[2], bl0[3]);
        mma_bf16(acc[1], al, bh0[2], bh0[3]);

        mma_bf16(acc[2], ah, bh1[0], bh1[1]);
        mma_bf16(acc[2], ah, bl1[0], bl1[1]);
        mma_bf16(acc[2], al, bh1[0], bh1[1]);

        mma_bf16(acc[3], ah, bh1[2], bh1[3]);
        mma_bf16(acc[3], ah, bl1[2], bl1[3]);
        mma_bf16(acc[3], al, bh1[2], bh1[3]);

        if (more) {
            if (buf == 0) { *(uint4*)AsmDst1 = pa; *(uint4*)BsmH1 = pb0; *(uint4*)BsmL1 = pb1; }
            else          { *(uint4*)AsmDst0 = pa; *(uint4*)BsmH0 = pb0; *(uint4*)BsmL0 = pb1; }
        }
        __syncthreads();
        buf ^= 1;
    }

    float* af = reinterpret_cast<float*>(acc);
    if (warp_k == 1) {
        int base = (wid - 4) * 32 + lane;
        #pragma unroll
        for (int j = 0; j < 16; j++) red[j * 128 + base] = af[j];
    }
    __syncthreads();
    if (warp_k == 0) {
        int base = wid * 32 + lane;
        #pragma unroll
        for (int j = 0; j < 16; j++) af[j] += red[j * 128 + base];

        const int row0 = rowBase + warp_m * 16 + (lane >> 2);
        #pragma unroll
        for (int nt = 0; nt < 4; nt++) {
            const int col = colBase + warp_n * 32 + nt * 8 + 2 * (lane & 3);
            float2 bb = *(const float2*)(bias + col);
            float v00 = acc[nt].x + bb.x, v01 = acc[nt].y + bb.y;
            float v10 = acc[nt].z + bb.x, v11 = acc[nt].w + bb.y;
            if (act == 1) {
                v00 = (v00 > 0.f) ? (v00 + 1.f) : expf(v00);
                v01 = (v01 > 0.f) ? (v01 + 1.f) : expf(v01);
                v10 = (v10 > 0.f) ? (v10 + 1.f) : expf(v10);
                v11 = (v11 > 0.f) ? (v11 + 1.f) : expf(v11);
            } else if (act == 2) {
                v00 = fmaxf(v00, 0.f); v01 = fmaxf(v01, 0.f);
                v10 = fmaxf(v10, 0.f); v11 = fmaxf(v11, 0.f);
            }
            if (outmode & 1) {
                *(float2*)(Cf32 + (size_t)row0 * N + col)       = make_float2(v00, v01);
                *(float2*)(Cf32 + (size_t)(row0 + 8) * N + col) = make_float2(v10, v11);
            }
            if (outmode & 2) {
                split_store(v00, Shi, Slo, (size_t)row0 * N + col);
                split_store(v01, Shi, Slo, (size_t)row0 * N + col + 1);
                split_store(v10, Shi, Slo, (size_t)(row0 + 8) * N + col);
                split_store(v11, Shi, Slo, (size_t)(row0 + 8) * N + col + 1);
            }
        }
    }
}

__global__ void gemm_bf16_kernel(int a_code, size_t w_off, const float* __restrict__ bias,
                                 int N, int K, int act, int outmode, int c_code, int s_code)
{
    float* Cf32 = (outmode & 1) ? scratch(c_code) : nullptr;
    bf16* Shi = (outmode & 2) ? split_hi_w(s_code) : nullptr;
    bf16* Slo = (outmode & 2) ? split_lo_w(s_code) : nullptr;
    gemm_bf16_core(split_hi(a_code), split_lo(a_code),
                   s_W_hi + w_off, s_W_lo + w_off, bias,
                   Cf32, Shi, Slo, N, K,
                   blockIdx.y * CTM, blockIdx.x * CTN, act, outmode);
}

__global__ void gemm_qkv_bf16_kernel(size_t offq, size_t offk, size_t offv,
                                     const float* __restrict__ bq,
                                     const float* __restrict__ bk,
                                     const float* __restrict__ bv)
{
    const int gcol = blockIdx.x * CTN;
    const int mat  = gcol / DM_;
    const int colBase = gcol - mat * DM_;
    size_t w_off      = (mat == 0) ? offq : (mat == 1) ? offk : offv;
    const float* bias = (mat == 0) ? bq   : (mat == 1) ? bk   : bv;
    bf16* shi         = (mat == 0) ? s_q_hi : (mat == 1) ? s_k_hi : s_v_hi;
    bf16* slo         = (mat == 0) ? s_q_lo : (mat == 1) ? s_k_lo : s_v_lo;
    const int act     = (mat < 2) ? 1 : 0;
    gemm_bf16_core(s_h_hi, s_h_lo, s_W_hi + w_off, s_W_lo + w_off, bias,
                   nullptr, shi, slo, DM_, DM_,
                   blockIdx.y * CTM, colBase, act, 2);
}

// ---------------------------------------------------------------------------
// Tensor-core causal linear attention, query-chunked + double-buffered.
// Grid (5 mchunks, 32 bh), 256 threads / 8 warps.
// Phase A: Q resident; K streamed in 32-d chunks (6 rounds, dbl-buffered).
// Phase C: S resident; V streamed in 16-tau chunks (dbl-buffered).
// Smem pool layout (bf16 elems):
//   [0,12800)   : K dbl-buf (buf,plane)*3200, rows W x 40   | V (buf,plane)*3200, rows 16 x 200
//   [12800,19200): Q (plane)*3200, rows 16 x 200
// ---------------------------------------------------------------------------
#define SLD 88      // S row stride (80 + 8 pad)
#define QP  200     // Q / V row stride (192 + 8 pad)
#define KP  40      // K chunk row stride (32 + 8 pad)

__device__ __forceinline__ void split2smem(float v, bf16* hi, bf16* lo, int idx)
{
    bf16 h = __float2bfloat16_rn(v);
    hi[idx] = h;
    lo[idx] = __float2bfloat16_rn(v - __bfloat162float(h));
}

__global__ void attn_mma_kernel()
{
    __shared__ __align__(16) bf16 pool[19200];       // 38.4 KB
    __shared__ __align__(16) bf16 sSh[16 * SLD];     // 2816 B
    __shared__ __align__(16) bf16 sSl[16 * SLD];
    __shared__ float inv_s[16];

    const int mc = blockIdx.x;           // 0..4
    const int bh = blockIdx.y;           // 0..31
    const int b = bh >> 2, h = bh & 3;
    const int t0 = mc * 16;
    const int W  = (mc + 1) * 16;
    const int tid = threadIdx.x, lane = tid & 31, wid = tid >> 5;
    const int g = lane >> 2, tq = lane & 3;

    const size_t rowB = (size_t)b * DM_ + h * DH_;   // helper offset piece

    // ---------------- Phase A: S = Q K^T ----------------
    float4 accA[2] = {{0,0,0,0},{0,0,0,0}};

    // Q resident load: 16 rows x 192 cols x 2 planes = 768 uint4
    for (int i = tid; i < 768; i += 256) {
        int p = i / 384, rem = i - p * 384;
        int row = rem / 24, c8 = rem - row * 24;
        const bf16* src = p ? s_q_lo : s_q_hi;
        *(uint4*)&pool[12800 + p * 3200 + row * QP + c8 * 8] =
            *(const uint4*)&src[(size_t)(t0 + row) * BS_ * DM_ + rowB + c8 * 8];
    }
    // K chunk 0 into buf 0
    {
        const int nld = W * 8;
        for (int i = tid; i < nld; i += 256) {
            int p = i / (W * 4), rem = i - p * (W * 4);
            int row = rem >> 2, c4 = rem & 3;
            const bf16* src = p ? s_k_lo : s_k_hi;
            *(uint4*)&pool[p * 3200 + row * KP + c4 * 8] =
                *(const uint4*)&src[(size_t)row * BS_ * DM_ + rowB + c4 * 8];
        }
    }
    __syncthreads();

    int buf = 0;
    for (int kc = 0; kc < 6; kc++) {
        if (wid <= mc) {
            #pragma unroll
            for (int x = 0; x < 2; x++) {
                uint32_t qh[4], ql[4], kh[4], kl[4];
                int qoff = (lane & 15) * QP + kc * 32 + x * 16 + ((lane >> 4) << 3);
                int koff = (wid * 16 + (lane & 15)) * KP + x * 16 + ((lane >> 4) << 3);
                ldm_x4(qh, smem_u32(&pool[12800 + qoff]));
                ldm_x4(ql, smem_u32(&pool[16000 + qoff]));
                ldm_x4(kh, smem_u32(&pool[(buf * 2) * 3200 + koff]));
                ldm_x4(kl, smem_u32(&pool[(buf * 2 + 1) * 3200 + koff]));
                mma_bf16(accA[0], qh, kh[0], kh[2]);
                mma_bf16(accA[0], qh, kl[0], kl[2]);
                mma_bf16(accA[0], ql, kh[0], kh[2]);
                mma_bf16(accA[1], qh, kh[1], kh[3]);
                mma_bf16(accA[1], qh, kl[1], kl[3]);
                mma_bf16(accA[1], ql, kh[1], kh[3]);
            }
        }
        if (kc < 5) {   // load next K chunk into other buffer
            const int nld = W * 8;
            const int cbase = (kc + 1) * 32;
            for (int i = tid; i < nld; i += 256) {
                int p = i / (W * 4), rem = i - p * (W * 4);
                int row = rem >> 2, c4 = rem & 3;
                const bf16* src = p ? s_k_lo : s_k_hi;
                *(uint4*)&pool[((buf ^ 1) * 2 + p) * 3200 + row * KP + c4 * 8] =
                    *(const uint4*)&src[(size_t)row * BS_ * DM_ + rowB + cbase + c4 * 8];
            }
        }
        __syncthreads();
        buf ^= 1;
    }

    // masked split store of S chunk (warp w -> cols [16w,16w+16))
    if (wid <= mc) {
        int r0 = g, r1 = g + 8;
        #pragma unroll
        for (int n8 = 0; n8 < 2; n8++) {
            int c = wid * 16 + n8 * 8 + 2 * tq;
            float4 a = accA[n8];
            split2smem((c     <= t0 + r0) ? a.x : 0.f, sSh, sSl, r0 * SLD + c);
            split2smem((c + 1 <= t0 + r0) ? a.y : 0.f, sSh, sSl, r0 * SLD + c + 1);
            split2smem((c     <= t0 + r1) ? a.z : 0.f, sSh, sSl, r1 * SLD + c);
            split2smem((c + 1 <= t0 + r1) ? a.w : 0.f, sSh, sSl, r1 * SLD + c + 1);
        }
    }
    __syncthreads();

    // rowsum (tid<16) + preload V chunk 0 into buf 0 (all threads)
    for (int i = tid; i < 768; i += 256) {
        int p = i / 384, rem = i - p * 384;
        int row = rem / 24, c8 = rem - row * 24;
        const bf16* src = p ? s_v_lo : s_v_hi;
        *(uint4*)&pool[p * 3200 + row * QP + c8 * 8] =
            *(const uint4*)&src[(size_t)row * BS_ * DM_ + rowB + c8 * 8];
    }
    if (tid < 16) {
        float s = 0.0f;
        for (int c = 0; c < W; c++)
            s += __bfloat162float(sSh[tid * SLD + c]) + __bfloat162float(sSl[tid * SLD + c]);
        inv_s[tid] = 1.0f / (s + EPS_ATT);
    }
    __syncthreads();

    // ---------------- Phase C: O = S V ----------------
    float4 accC[2][2];
    #pragma unroll
    for (int j = 0; j < 2; j++) { accC[j][0] = make_float4(0,0,0,0); accC[j][1] = make_float4(0,0,0,0); }

    buf = 0;
    for (int vc = 0; vc <= mc; vc++) {
        uint32_t sh[4], sl[4];
        int aoff = (lane & 15) * SLD + vc * 16 + ((lane >> 4) << 3);
        ldm_x4(sh, smem_u32(&sSh[aoff]));
        ldm_x4(sl, smem_u32(&sSl[aoff]));

        #pragma unroll
        for (int j = 0; j < 2; j++) {
            int ni = wid + 8 * j;
            if (ni < 12) {
                uint32_t vh[4], vl[4];
                int boff = (lane & 15) * QP + ni * 16 + ((lane >> 4) << 3);
                ldm_x4_t(vh, smem_u32(&pool[(buf * 2) * 3200 + boff]));
                ldm_x4_t(vl, smem_u32(&pool[(buf * 2 + 1) * 3200 + boff]));
                mma_bf16(accC[j][0], sh, vh[0], vh[1]);
                mma_bf16(accC[j][0], sh, vl[0], vl[1]);
                mma_bf16(accC[j][0], sl, vh[0], vh[1]);
                mma_bf16(accC[j][1], sh, vh[2], vh[3]);
                mma_bf16(accC[j][1], sh, vl[2], vl[3]);
                mma_bf16(accC[j][1], sl, vh[2], vh[3]);
            }
        }

        if (vc < mc) {   // load next V chunk into other buffer
            const int rbase = (vc + 1) * 16;
            for (int i = tid; i < 768; i += 256) {
                int p = i / 384, rem = i - p * 384;
                int row = rem / 24, c8 = rem - row * 24;
                const bf16* src = p ? s_v_lo : s_v_hi;
                *(uint4*)&pool[((buf ^ 1) * 2 + p) * 3200 + row * QP + c8 * 8] =
                    *(const uint4*)&src[(size_t)(rbase + row) * BS_ * DM_ + rowB + c8 * 8];
            }
        }
        __syncthreads();
        buf ^= 1;
    }

    // output: scale by inv, split-store to s_att
    {
        int r0 = g, r1 = g + 8;
        float i0 = inv_s[r0], i1 = inv_s[r1];
        #pragma unroll
        for (int j = 0; j < 2; j++) {
            int ni = wid + 8 * j;
            if (ni < 12) {
                #pragma unroll
                for (int n8 = 0; n8 < 2; n8++) {
                    int d = ni * 16 + n8 * 8 + 2 * tq;
                    float4 a = accC[j][n8];
                    size_t o0 = (size_t)(t0 + r0) * BS_ * DM_ + rowB + d;
                    size_t o1 = (size_t)(t0 + r1) * BS_ * DM_ + rowB + d;
                    split_store(a.x * i0, s_att_hi, s_att_lo, o0);
                    split_store(a.y * i0, s_att_hi, s_att_lo, o0 + 1);
                    split_store(a.z * i1, s_att_hi, s_att_lo, o1);
                    split_store(a.w * i1, s_att_hi, s_att_lo, o1 + 1);
                }
            }
        }
    }
}

// ---------------------------------------------------------------------------
// LayerNorm helpers
// ---------------------------------------------------------------------------
__device__ __forceinline__ float block_sum_256(float val)
{
    __shared__ float sh[8];
    const int lane = threadIdx.x & 31;
    const int w    = threadIdx.x >> 5;
    #pragma unroll
    for (int o = 16; o > 0; o >>= 1) val += __shfl_down_sync(0xffffffffu, val, o);
    if (lane == 0) sh[w] = val;
    __syncthreads();
    if (w == 0) {
        float r = (lane < 8) ? sh[lane] : 0.0f;
        #pragma unroll
        for (int o = 4; o > 0; o >>= 1) r += __shfl_down_sync(0xffffffffu, r, o);
        if (lane == 0) sh[0] = r;
    }
    __syncthreads();
    float res = sh[0];
    __syncthreads();
    return res;
}

__global__ void ln_residual_kernel(int x_code, int y_code,
                                   const float* __restrict__ g, const float* __restrict__ bt,
                                   int out_code, int s_code)
{
    const float* x  = scratch(x_code);
    const float* yv = scratch(y_code);
    float* out      = scratch(out_code);
    bf16* shi = split_hi_w(s_code);
    bf16* slo = split_lo_w(s_code);

    const int row = blockIdx.x;
    const int tid = threadIdx.x;
    const size_t base = (size_t)row * DM_;

    float v0 = x[base + tid]       + yv[base + tid];
    float v1 = x[base + tid + 256] + yv[base + tid + 256];
    float v2 = x[base + tid + 512] + yv[base + tid + 512];

    float mean = block_sum_256(v0 + v1 + v2) * (1.0f / (float)DM_);
    float d0 = v0 - mean, d1 = v1 - mean, d2 = v2 - mean;
    float var = block_sum_256(d0*d0 + d1*d1 + d2*d2) * (1.0f / (float)DM_);
    float rstd = rsqrtf(var + EPS_LN);

    float o0 = d0 * rstd * g[tid]       + bt[tid];
    float o1 = d1 * rstd * g[tid + 256] + bt[tid + 256];
    float o2 = d2 * rstd * g[tid + 512] + bt[tid + 512];

    out[base + tid]       = o0;
    out[base + tid + 256] = o1;
    out[base + tid + 512] = o2;
    split_store(o0, shi, slo, base + tid);
    split_store(o1, shi, slo, base + tid + 256);
    split_store(o2, shi, slo, base + tid + 512);
}

// ---------------------------------------------------------------------------
// Final gather + LN
// ---------------------------------------------------------------------------
__global__ void gather_kernel(const int* __restrict__ act_ts,
                              const float* __restrict__ g, const float* __restrict__ bt,
                              float* __restrict__ out)
{
    const int ba = blockIdx.x;
    const int b  = ba / A_;
    int t = act_ts[ba] - 1;
    if (t < 0) t = 0;
    const int row = t * BS_ + b;
    const int tid = threadIdx.x;
    const size_t base = (size_t)row * DM_;

    float v0 = g_h[base + tid];
    float v1 = g_h[base + tid + 256];
    float v2 = g_h[base + tid + 512];

    float mean = block_sum_256(v0 + v1 + v2) * (1.0f / (float)DM_);
    float d0 = v0 - mean, d1 = v1 - mean, d2 = v2 - mean;
    float var = block_sum_256(d0*d0 + d1*d1 + d2*d2) * (1.0f / (float)DM_);
    float rstd = rsqrtf(var + EPS_LN);

    out[(size_t)ba * LATENT_ + tid]                      = d0 * rstd * g[tid]       + bt[tid];
    out[(size_t)BS_ * A_ * LATENT_ + ba * LATENT_ + tid] = d1 * rstd * g[tid + 256] + bt[tid + 256];
}

// ---------------------------------------------------------------------------
// Host orchestration: kernel launches ONLY
// ---------------------------------------------------------------------------
extern "C" void kernel_launch(void* const* d_in, const int* in_sizes, int n_in,
                              void* d_out, int out_size)
{
    const float* x    = (const float*)d_in[0];
    const int*   y    = (const int*)  d_in[1];
    const int*   ind  = (const int*)  d_in[2];
    const int*   ats  = (const int*)  d_in[3];
    const float* skW  = (const float*)d_in[4];
    const float* skb  = (const float*)d_in[5];
    const float* muQ  = (const float*)d_in[6];
    const float* sgQ  = (const float*)d_in[7];
    const float* Wq   = (const float*)d_in[8];
    const float* bq   = (const float*)d_in[9];
    const float* Wk   = (const float*)d_in[10];
    const float* bk   = (const float*)d_in[11];
    const float* Wv   = (const float*)d_in[12];
    const float* bv   = (const float*)d_in[13];
    const float* Wo   = (const float*)d_in[14];
    const float* bo   = (const float*)d_in[15];
    const float* W1   = (const float*)d_in[16];
    const float* b1   = (const float*)d_in[17];
    const float* W2   = (const float*)d_in[18];
    const float* b2   = (const float*)d_in[19];
    const float* l1g  = (const float*)d_in[20];
    const float* l1b  = (const float*)d_in[21];
    const float* l2g  = (const float*)d_in[22];
    const float* l2b  = (const float*)d_in[23];
    const float* lfg  = (const float*)d_in[24];
    const float* lfb  = (const float*)d_in[25];
    float* out = (float*)d_out;

    split_weights_kernel<<<(unsigned)((TOTALW / 4 + 255) / 256), 256>>>(Wq, Wk, Wv, Wo, W1, W2);
    build_h0_kernel<<<ROWS_, 256>>>(x, y, ind, skW, skb, muQ, sgQ);

    const dim3 gQKV(3 * DM_ / CTN, ROWS_ / CTM);   // 36 x 20
    const dim3 g768(DM_ / CTN, ROWS_ / CTM);       // 12 x 20
    const dim3 g1024(FF_ / CTN, ROWS_ / CTM);      // 16 x 20
    const dim3 gAttn(5, BS_ * H_);                 // 160 blocks

    const size_t szAttL = (size_t)DM_ * DM_;
    const size_t szFFL  = (size_t)DM_ * FF_;

    for (int l = 0; l < L_; l++) {
        gemm_qkv_bf16_kernel<<<gQKV, 256>>>(OFF_WQ + l * szAttL,
                                            OFF_WK + l * szAttL,
                                            OFF_WV + l * szAttL,
                                            bq + l * DM_, bk + l * DM_, bv + l * DM_);
        attn_mma_kernel<<<gAttn, 256>>>();
        gemm_bf16_kernel<<<g768, 256>>>(SPL_ATT, OFF_WO + l * szAttL, bo + l * DM_,
                                        DM_, DM_, 0, 1, BUF_Q, 0);
        ln_residual_kernel<<<ROWS_, 256>>>(BUF_H, BUF_Q, l1g + l * DM_, l1b + l * DM_,
                                           BUF_H1, SPL_H1);
        gemm_bf16_kernel<<<g1024, 256>>>(SPL_H1, OFF_W1 + l * szFFL, b1 + l * FF_,
                                         FF_, DM_, 2, 2, 0, SPL_FF);
        gemm_bf16_kernel<<<g768, 256>>>(SPL_FF, OFF_W2 + l * szFFL, b2 + l * DM_,
                                        DM_, FF_, 0, 1, BUF_Q, 0);
        ln_residual_kernel<<<ROWS_, 256>>>(BUF_H1, BUF_Q, l2g + l * DM_, l2b + l * DM_,
                                           BUF_H, SPL_H);
    }

    gather_kernel<<<BS_ * A_, 256>>>(ats, lfg, lfb, out);
}